// round 9
// baseline (speedup 1.0000x reference)
#include <cuda_runtime.h>
#include <cuda_bf16.h>
#include <cstdint>
#include <cstddef>

#define BB 8
#define CC 256
#define HH 64
#define WW 64
#define GG 8
#define CGR 32
#define KKT 9
#define OO 256
#define NPIX (BB*HH*WW)        // 32768
#define KC (CC*KKT)            // 2304
#define KW (KC/2)              // 1152 b32 words per row
#define CO1 216
#define HWSZ (HH*WW)           // 4096
#define NCH (KC/16)            // 144 k16 steps

// smem rings: B 4 stages x 16KB (hi 8K | lo 8K); A 4 stages x 4KB (hi 2K | lo 2K)
#define B_STG_B 16384
#define A_BASE  65536
#define A_STG_B 4096
#define SMEM_TOT (A_BASE + 4*A_STG_B)   // 81920

// -------- scratch (static device globals, ~382MB) -------------------------
__device__ __align__(16) float    g_Y[(size_t)CO1 * NPIX];          // conv1 out
__device__ __align__(16) float4   g_wq[(size_t)(GG*KKT) * NPIX];    // bilinear wts * attn
__device__ __align__(16) int      g_idx[(size_t)(GG*KKT) * NPIX];   // packed indices
__device__ __align__(16) uint32_t g_Bw[2][2][256 * KW];             // [gemm][hi/lo][n][kw]
__device__ __align__(16) uint16_t g_Ah[(size_t)KC * NPIX];          // sampled A hi plane
__device__ __align__(16) uint16_t g_Al[(size_t)KC * NPIX];          // sampled A lo plane

// -------- helpers ---------------------------------------------------------
__device__ __forceinline__ uint32_t smem_u32(const void* p) {
    uint32_t a;
    asm("{ .reg .u64 t; cvta.to.shared.u64 t, %1; cvt.u32.u64 %0, t; }"
        : "=r"(a) : "l"(p));
    return a;
}
__device__ __forceinline__ void cpasync16(uint32_t dst, const void* src) {
    asm volatile("cp.async.cg.shared.global [%0], [%1], 16;"
        :: "r"(dst), "l"(src) : "memory");
}
#define CP_COMMIT() asm volatile("cp.async.commit_group;" ::: "memory")
#define CP_WAIT2()  asm volatile("cp.async.wait_group 2;" ::: "memory")
#define CP_WAIT0()  asm volatile("cp.async.wait_group 0;" ::: "memory")
__device__ __forceinline__ void ldsm4(uint32_t* r, uint32_t addr) {
    asm volatile("ldmatrix.sync.aligned.m8n8.x4.shared.b16 {%0,%1,%2,%3}, [%4];"
        : "=r"(r[0]), "=r"(r[1]), "=r"(r[2]), "=r"(r[3]) : "r"(addr));
}
__device__ __forceinline__ void ldsm4t(uint32_t* r, uint32_t addr) {
    asm volatile("ldmatrix.sync.aligned.m8n8.x4.trans.shared.b16 {%0,%1,%2,%3}, [%4];"
        : "=r"(r[0]), "=r"(r[1]), "=r"(r[2]), "=r"(r[3]) : "r"(addr));
}
__device__ __forceinline__ void mma16816(float* c, const uint32_t* a,
                                         uint32_t b0, uint32_t b1) {
    asm volatile(
        "mma.sync.aligned.m16n8k16.row.col.f32.bf16.bf16.f32 "
        "{%0,%1,%2,%3}, {%4,%5,%6,%7}, {%8,%9}, {%0,%1,%2,%3};"
        : "+f"(c[0]), "+f"(c[1]), "+f"(c[2]), "+f"(c[3])
        : "r"(a[0]), "r"(a[1]), "r"(a[2]), "r"(a[3]), "r"(b0), "r"(b1));
}
__device__ __forceinline__ void split_bf16(float v, uint16_t& h, uint16_t& l) {
    __nv_bfloat16 hb = __float2bfloat16(v);
    float r = v - __bfloat162float(hb);
    __nv_bfloat16 lb = __float2bfloat16(r);
    h = *reinterpret_cast<uint16_t*>(&hb);
    l = *reinterpret_cast<uint16_t*>(&lb);
}

// -------- setup: split weights to bf16 hi/lo word pairs -------------------
__global__ __launch_bounds__(256) void stageB_kernel(
    const float* __restrict__ w_off, const float* __restrict__ w_attn,
    const float* __restrict__ w_out)
{
    int idx = blockIdx.x * 256 + threadIdx.x;     // over 2*256*1152
    int gemm = idx / (256 * KW);
    int rem  = idx - gemm * (256 * KW);
    int row  = rem / KW;
    int wd   = rem - row * KW;
    int k    = wd * 2;
    float v0 = 0.f, v1 = 0.f;
    if (gemm == 0) {
        if (row < 144) {
            v0 = w_off[(size_t)row * KC + k];
            v1 = w_off[(size_t)row * KC + k + 1];
        } else if (row < CO1) {
            v0 = w_attn[(size_t)(row - 144) * KC + k];
            v1 = w_attn[(size_t)(row - 144) * KC + k + 1];
        }
    } else {
        v0 = w_out[(size_t)row * KC + k];
        v1 = w_out[(size_t)row * KC + k + 1];
    }
    uint16_t h0, l0, h1, l1;
    split_bf16(v0, h0, l0);
    split_bf16(v1, h1, l1);
    g_Bw[gemm][0][row * KW + wd] = (uint32_t)h0 | ((uint32_t)h1 << 16);
    g_Bw[gemm][1][row * KW + wd] = (uint32_t)l0 | ((uint32_t)l1 << 16);
}

// -------- main warp-MMA implicit GEMM -------------------------------------
// CTA: 64 pixels x 256 channels, K = 2304. 256 threads / 8 warps (2m x 4n),
// 2 CTAs per SM for latency hiding.
// EPI==0: A = im2col(x) computed in-kernel (2-stage STS ring); B cp.async 4-stage
// EPI==1: A & B pure cp.async copies, both 4-stage rings
template <int EPI>
__global__ __launch_bounds__(256, 2) void mma_kernel(
    const float* __restrict__ x,
    const float* __restrict__ ba,
    const float* __restrict__ bb,
    float* __restrict__ Cout)
{
    constexpr int ASTG = (EPI == 0) ? 2 : 4;
    extern __shared__ __align__(16) char smem[];
    const uint32_t sb = smem_u32(smem);
    const int tid  = threadIdx.x;
    const int lane = tid & 31;
    const int wid  = tid >> 5;
    const int wm   = wid & 1;      // warp m-index (x32)
    const int wn   = wid >> 1;     // warp n-index (x64)
    const int m0   = blockIdx.x * 64;
    const int b    = m0 >> 12;

    // EPI0 producer mapping: m row + word pair
    const int pm = tid >> 2;       // 0..63
    const int pq = tid & 3;        // word pair (words pq*2, pq*2+1)

    // EPI1 A-copy mapping: (plane, k-row, 16B seg)
    const int cs  = tid & 7;             // seg (8 x 16B = 128B row)
    const int ckl = (tid >> 3) & 15;     // k-row
    const int cpl = (tid >> 7) & 1;      // 0 hi, 1 lo

    // ---- ldmatrix per-lane offsets (relative to stage bases) ----
    int offAh[2], offBh[4];
    if (EPI == 0) {
        const int rA   = lane & 15;
        const int segA = lane >> 4;
#pragma unroll
        for (int mt = 0; mt < 2; mt++) {
            int row = wm * 32 + mt * 16 + rA;
            offAh[mt] = row * 32 + (((segA * 4) ^ (rA & 4)) << 2);
        }
    } else {
        const int kr = (lane & 7) + ((lane & 16) ? 8 : 0);
        const int mo = (lane & 8) ? 1 : 0;
#pragma unroll
        for (int mt = 0; mt < 2; mt++) {
            int mseg = wm * 4 + mt * 2 + mo;     // 0..7
            offAh[mt] = kr * 128 + ((mseg ^ (kr & 7)) << 4);
        }
    }
    {
        const int rB   = (lane & 7) + ((lane & 16) ? 8 : 0);
        const int segB = (lane >> 3) & 1;
#pragma unroll
        for (int ntp = 0; ntp < 4; ntp++) {
            int row = wn * 64 + ntp * 16 + rB;
            offBh[ntp] = row * 32 + (((segB * 4) ^ (rB & 4)) << 2);
        }
    }

    float cr[2][8][4];
#pragma unroll
    for (int mt = 0; mt < 2; mt++)
#pragma unroll
        for (int nt = 0; nt < 8; nt++)
#pragma unroll
            for (int j = 0; j < 4; j++) cr[mt][nt][j] = 0.f;

    const uint32_t* __restrict__ Bh = g_Bw[EPI][0];
    const uint32_t* __restrict__ Bl = g_Bw[EPI][1];

    // ---- async producers ----
    auto cpB = [&](int c) {
        if (c < NCH) {
            // B: thread owns row tid; two 16B segs per plane
            uint32_t bst = sb + (c & 3) * B_STG_B;
            const uint32_t* sh = &Bh[tid * KW + c * 8];
            const uint32_t* sl = &Bl[tid * KW + c * 8];
#pragma unroll
            for (int seg = 0; seg < 2; seg++) {
                uint32_t dby = (tid * 8 + ((seg * 4) ^ (tid & 4))) * 4;
                cpasync16(bst + dby, sh + seg * 4);
                cpasync16(bst + 8192 + dby, sl + seg * 4);
            }
            if (EPI == 1) {
                // A: 16 k-rows x 64 pixels x 2B per plane (2KB), k-major swizzled
                uint32_t adst = sb + A_BASE + (c & 3) * A_STG_B + cpl * 2048
                              + ckl * 128 + ((cs ^ (ckl & 7)) << 4);
                const uint16_t* src = (cpl ? g_Al : g_Ah)
                    + (size_t)(c * 16 + ckl) * NPIX + m0 + cs * 8;
                cpasync16(adst, src);
            }
        }
        CP_COMMIT();
    };
    auto prodA0 = [&](int c) {      // EPI0 only: compute + STS (m-major)
        if (c >= NCH) return;
        char* stp = smem + A_BASE + (c % ASTG) * A_STG_B;
        const int mg = m0 + pm;
        const int hh = (mg & 4095) >> 6;
        const int ww = mg & 63;
#pragma unroll
        for (int u = 0; u < 2; u++) {
            const int w = pq * 2 + u;            // word 0..7
            const int k = c * 16 + w * 2;
            float v0, v1;
#pragma unroll
            for (int t = 0; t < 2; t++) {
                int kk  = k + t;
                int ci  = kk / 9;
                int tap = kk - ci * 9;
                int dy = tap / 3 - 1, dx = tap - (tap / 3) * 3 - 1;
                int y = hh + dy, xx2 = ww + dx;
                float v = ((unsigned)y < (unsigned)HH &&
                           (unsigned)xx2 < (unsigned)WW)
                    ? x[((size_t)(b * CC + ci) << 12) + (y << 6) + xx2] : 0.f;
                if (t == 0) v0 = v; else v1 = v;
            }
            uint16_t h0, l0, h1, l1;
            split_bf16(v0, h0, l0);
            split_bf16(v1, h1, l1);
            int dw = pm * 8 + (w ^ (pm & 4));
            *(uint32_t*)(stp +        dw * 4) = (uint32_t)h0 | ((uint32_t)h1 << 16);
            *(uint32_t*)(stp + 2048 + dw * 4) = (uint32_t)l0 | ((uint32_t)l1 << 16);
        }
    };

    // ---- prologue: 3 async groups in flight; EPI0 also computes A(0) ----
    cpB(0); cpB(1); cpB(2);
    if (EPI == 0) prodA0(0);

    for (int c = 0; c < NCH; c++) {
        CP_WAIT2();               // stage c resident
        __syncthreads();          // + all warps done reading recycled stages

        if (EPI == 0) prodA0(c + 1);
        cpB(c + 3);

        // ---- consume stage c ----
        const uint32_t stbB = sb + (c & 3) * B_STG_B;
        const uint32_t stbA = sb + A_BASE + (c % ASTG) * A_STG_B;
        uint32_t ah[2][4], al[2][4];
#pragma unroll
        for (int mt = 0; mt < 2; mt++) {
            if (EPI == 0) {
                ldsm4(ah[mt], stbA + offAh[mt]);
                ldsm4(al[mt], stbA + offAh[mt] + 2048);
            } else {
                ldsm4t(ah[mt], stbA + offAh[mt]);
                ldsm4t(al[mt], stbA + offAh[mt] + 2048);
            }
        }
#pragma unroll
        for (int ntp = 0; ntp < 4; ntp++) {
            uint32_t bh[4], bl[4];
            ldsm4(bh, stbB + offBh[ntp]);
            ldsm4(bl, stbB + offBh[ntp] + 8192);
#pragma unroll
            for (int j = 0; j < 2; j++) {
                const int nt = ntp * 2 + j;
#pragma unroll
                for (int mt = 0; mt < 2; mt++) {
                    float* cc = cr[mt][nt];
                    mma16816(cc, ah[mt], bh[2 * j], bh[2 * j + 1]);
                    mma16816(cc, ah[mt], bl[2 * j], bl[2 * j + 1]);
                    mma16816(cc, al[mt], bh[2 * j], bh[2 * j + 1]);
                }
            }
        }
    }
    CP_WAIT0();

    // ---- epilogue ----
    const int eg = lane >> 2;
    const int et = lane & 3;
#pragma unroll
    for (int mt = 0; mt < 2; mt++) {
#pragma unroll
        for (int nt = 0; nt < 8; nt++) {
            const float* cc = cr[mt][nt];
            int mloc = wm * 32 + mt * 16 + eg;
            int co   = wn * 64 + nt * 8 + et * 2;
#pragma unroll
            for (int rr = 0; rr < 2; rr++) {
                int m = m0 + mloc + rr * 8;
#pragma unroll
                for (int cw = 0; cw < 2; cw++) {
                    int c2 = co + cw;
                    float v = cc[rr * 2 + cw];
                    if (EPI == 0) {
                        if (c2 < CO1) {
                            float bias = (c2 < 144) ? ba[c2] : bb[c2 - 144];
                            g_Y[(size_t)c2 * NPIX + m] = v + bias;
                        }
                    } else {
                        Cout[((size_t)(b * OO + c2) << 12) + (m & 4095)] = v + ba[c2];
                    }
                }
            }
        }
    }
}

// -------- softmax + offsets -> packed bilinear weights/indices ------------
__global__ __launch_bounds__(256) void offmask_kernel() {
    int n = blockIdx.x * 256 + threadIdx.x;
    int g = blockIdx.y;
    int hw = n & 4095;
    int h = hw >> 6, w = hw & 63;

    float lg[KKT];
    float mx = -1e30f;
#pragma unroll
    for (int kk = 0; kk < KKT; kk++) {
        lg[kk] = g_Y[(size_t)(144 + g * KKT + kk) * NPIX + n];
        mx = fmaxf(mx, lg[kk]);
    }
    float s = 0.f;
#pragma unroll
    for (int kk = 0; kk < KKT; kk++) { lg[kk] = __expf(lg[kk] - mx); s += lg[kk]; }
    float inv = 1.f / s;

#pragma unroll
    for (int kk = 0; kk < KKT; kk++) {
        float a  = lg[kk] * inv;
        float dy = g_Y[(size_t)(g * 18 + 2 * kk    ) * NPIX + n];
        float dx = g_Y[(size_t)(g * 18 + 2 * kk + 1) * NPIX + n];
        float py = (float)(h - 1 + kk / 3) + dy;
        float px = (float)(w - 1 + kk % 3) + dx;

        float y0f = floorf(py), x0f = floorf(px);
        float fy = py - y0f, fx = px - x0f;
        y0f = fminf(fmaxf(y0f, -2.f), 65.f);
        x0f = fminf(fmaxf(x0f, -2.f), 65.f);
        int y0 = (int)y0f, x0 = (int)x0f;

        bool vy0 = (unsigned)y0       < (unsigned)HH;
        bool vy1 = (unsigned)(y0 + 1) < (unsigned)HH;
        bool vx0 = (unsigned)x0       < (unsigned)WW;
        bool vx1 = (unsigned)(x0 + 1) < (unsigned)WW;

        float w00 = (vy0 && vx0) ? (1.f - fy) * (1.f - fx) * a : 0.f;
        float w01 = (vy0 && vx1) ? (1.f - fy) * fx * a : 0.f;
        float w10 = (vy1 && vx0) ? fy * (1.f - fx) * a : 0.f;
        float w11 = (vy1 && vx1) ? fy * fx * a : 0.f;

        int r0  = min(max(y0,     0), HH - 1);
        int r1  = min(max(y0 + 1, 0), HH - 1);
        int cc0 = min(max(x0,     0), WW - 1);
        int cc1 = min(max(x0 + 1, 0), WW - 1);
        int pack = r0 | (r1 << 6) | (cc0 << 12) | (cc1 << 18);

        size_t o = (size_t)(g * KKT + kk) * NPIX + n;
        g_wq[o]  = make_float4(w00, w01, w10, w11);
        g_idx[o] = pack;
    }
}

// -------- sampler: wq/idx once per (pixel,g,tap), loop cg, write planes ---
__global__ __launch_bounds__(256) void sample_kernel(const float* __restrict__ x) {
    int n  = blockIdx.x * 256 + threadIdx.x;
    int gk = blockIdx.y;               // 0..71
    int g = gk / KKT, tap = gk - g * KKT;
    int b = n >> 12;

    size_t sidx = (size_t)gk * NPIX + n;
    float4 wq = g_wq[sidx];
    int pk = g_idx[sidx];
    int r0 = pk & 63, r1 = (pk >> 6) & 63;
    int c0 = (pk >> 12) & 63, c1 = (pk >> 18) & 63;
    int o00 = (r0 << 6) + c0, o01 = (r0 << 6) + c1;
    int o10 = (r1 << 6) + c0, o11 = (r1 << 6) + c1;

    const float* xb = x + ((size_t)(b * CC + g * CGR) << 12);
    const int kbase = g * 288 + tap;
#pragma unroll 4
    for (int cg = 0; cg < CGR; cg++) {
        const float* p = xb + ((size_t)cg << 12);
        float v = wq.x * p[o00] + wq.y * p[o01] + wq.z * p[o10] + wq.w * p[o11];
        uint16_t h, l;
        split_bf16(v, h, l);
        size_t a = (size_t)(kbase + cg * 9) * NPIX + n;
        g_Ah[a] = h;
        g_Al[a] = l;
    }
}

// --------------------------------------------------------------------------
extern "C" void kernel_launch(void* const* d_in, const int* in_sizes, int n_in,
                              void* d_out, int out_size) {
    const float* x      = nullptr;
    const float* w_off  = nullptr;
    const float* b_off  = nullptr;
    const float* w_attn = nullptr;
    const float* b_attn = nullptr;
    const float* w_out  = nullptr;
    const float* b_out  = nullptr;
    for (int i = 0; i < n_in; i++) {
        const float* p = (const float*)d_in[i];
        switch (in_sizes[i]) {
            case 8388608: x      = p; break;
            case 331776:  w_off  = p; break;
            case 144:     b_off  = p; break;
            case 165888:  w_attn = p; break;
            case 72:      b_attn = p; break;
            case 589824:  w_out  = p; break;
            case 256:     b_out  = p; break;
            default: break;
        }
    }
    if (!x || !w_off || !b_off || !w_attn || !b_attn || !w_out || !b_out)
        return;
    float* out = (float*)d_out;

    cudaFuncSetAttribute(mma_kernel<0>,
        cudaFuncAttributeMaxDynamicSharedMemorySize, SMEM_TOT);
    cudaFuncSetAttribute(mma_kernel<1>,
        cudaFuncAttributeMaxDynamicSharedMemorySize, SMEM_TOT);

    // 0) stage weights: fp32 -> bf16 hi/lo packed word pairs
    stageB_kernel<<<(2 * 256 * KW) / 256, 256>>>(w_off, w_attn, w_out);

    // 1) offset/mask conv (HMMA, fused im2col, cp.async B) -> g_Y
    mma_kernel<0><<<NPIX / 64, 256, SMEM_TOT>>>(x, b_off, b_attn, nullptr);

    // 2) softmax + packed bilinear weights/indices
    offmask_kernel<<<dim3(NPIX / 256, GG), 256>>>();

    // 3) sampling pass: modulated bilinear gather -> bf16 hi/lo planes
    sample_kernel<<<dim3(NPIX / 256, GG * KKT), 256>>>(x);

    // 4) deformable conv (HMMA, A/B cp.async 4-stage) -> NCHW out
    mma_kernel<1><<<NPIX / 64, 256, SMEM_TOT>>>(x, b_out, nullptr, out);
}

// round 10
// speedup vs baseline: 1.3533x; 1.3533x over previous
#include <cuda_runtime.h>
#include <cuda_bf16.h>
#include <cstdint>
#include <cstddef>

#define BB 8
#define CC 256
#define HH 64
#define WW 64
#define GG 8
#define CGR 32
#define KKT 9
#define OO 256
#define NPIX (BB*HH*WW)        // 32768
#define KC (CC*KKT)            // 2304
#define KW (KC/2)              // 1152 b32 words per row
#define CO1 216
#define HWSZ (HH*WW)           // 4096
#define NCH (KC/16)            // 144 k16 steps

// smem rings: B 8 stages x 16KB (hi 8K | lo 8K); A 8 stages x 8KB (hi 4K | lo 4K)
#define B_STG_B 16384
#define A_BASE  131072
#define A_STG_B 8192
#define SMEM_TOT (A_BASE + 8*A_STG_B)   // 196608

// -------- scratch (static device globals, ~382MB) -------------------------
__device__ __align__(16) float    g_Y[(size_t)CO1 * NPIX];          // conv1 out
__device__ __align__(16) float4   g_wq[(size_t)(GG*KKT) * NPIX];    // bilinear wts * attn
__device__ __align__(16) int      g_idx[(size_t)(GG*KKT) * NPIX];   // packed indices
__device__ __align__(16) uint32_t g_Bw[2][2][256 * KW];             // [gemm][hi/lo][n][kw]
__device__ __align__(16) uint16_t g_Ah[(size_t)KC * NPIX];          // sampled A hi plane
__device__ __align__(16) uint16_t g_Al[(size_t)KC * NPIX];          // sampled A lo plane

// -------- helpers ---------------------------------------------------------
__device__ __forceinline__ uint32_t smem_u32(const void* p) {
    uint32_t a;
    asm("{ .reg .u64 t; cvta.to.shared.u64 t, %1; cvt.u32.u64 %0, t; }"
        : "=r"(a) : "l"(p));
    return a;
}
__device__ __forceinline__ void cpasync16(uint32_t dst, const void* src) {
    asm volatile("cp.async.cg.shared.global [%0], [%1], 16;"
        :: "r"(dst), "l"(src) : "memory");
}
#define CP_COMMIT() asm volatile("cp.async.commit_group;" ::: "memory")
#define CP_WAIT6()  asm volatile("cp.async.wait_group 6;" ::: "memory")
#define CP_WAIT0()  asm volatile("cp.async.wait_group 0;" ::: "memory")
__device__ __forceinline__ void ldsm4(uint32_t* r, uint32_t addr) {
    asm volatile("ldmatrix.sync.aligned.m8n8.x4.shared.b16 {%0,%1,%2,%3}, [%4];"
        : "=r"(r[0]), "=r"(r[1]), "=r"(r[2]), "=r"(r[3]) : "r"(addr));
}
__device__ __forceinline__ void ldsm4t(uint32_t* r, uint32_t addr) {
    asm volatile("ldmatrix.sync.aligned.m8n8.x4.trans.shared.b16 {%0,%1,%2,%3}, [%4];"
        : "=r"(r[0]), "=r"(r[1]), "=r"(r[2]), "=r"(r[3]) : "r"(addr));
}
__device__ __forceinline__ void mma16816(float* c, const uint32_t* a,
                                         uint32_t b0, uint32_t b1) {
    asm volatile(
        "mma.sync.aligned.m16n8k16.row.col.f32.bf16.bf16.f32 "
        "{%0,%1,%2,%3}, {%4,%5,%6,%7}, {%8,%9}, {%0,%1,%2,%3};"
        : "+f"(c[0]), "+f"(c[1]), "+f"(c[2]), "+f"(c[3])
        : "r"(a[0]), "r"(a[1]), "r"(a[2]), "r"(a[3]), "r"(b0), "r"(b1));
}
__device__ __forceinline__ void split_bf16(float v, uint16_t& h, uint16_t& l) {
    __nv_bfloat16 hb = __float2bfloat16(v);
    float r = v - __bfloat162float(hb);
    __nv_bfloat16 lb = __float2bfloat16(r);
    h = *reinterpret_cast<uint16_t*>(&hb);
    l = *reinterpret_cast<uint16_t*>(&lb);
}

// -------- setup: split weights to bf16 hi/lo word pairs -------------------
__global__ __launch_bounds__(256) void stageB_kernel(
    const float* __restrict__ w_off, const float* __restrict__ w_attn,
    const float* __restrict__ w_out)
{
    int idx = blockIdx.x * 256 + threadIdx.x;     // over 2*256*1152
    int gemm = idx / (256 * KW);
    int rem  = idx - gemm * (256 * KW);
    int row  = rem / KW;
    int wd   = rem - row * KW;
    int k    = wd * 2;
    float v0 = 0.f, v1 = 0.f;
    if (gemm == 0) {
        if (row < 144) {
            v0 = w_off[(size_t)row * KC + k];
            v1 = w_off[(size_t)row * KC + k + 1];
        } else if (row < CO1) {
            v0 = w_attn[(size_t)(row - 144) * KC + k];
            v1 = w_attn[(size_t)(row - 144) * KC + k + 1];
        }
    } else {
        v0 = w_out[(size_t)row * KC + k];
        v1 = w_out[(size_t)row * KC + k + 1];
    }
    uint16_t h0, l0, h1, l1;
    split_bf16(v0, h0, l0);
    split_bf16(v1, h1, l1);
    g_Bw[gemm][0][row * KW + wd] = (uint32_t)h0 | ((uint32_t)h1 << 16);
    g_Bw[gemm][1][row * KW + wd] = (uint32_t)l0 | ((uint32_t)l1 << 16);
}

// -------- main warp-MMA implicit GEMM -------------------------------------
// CTA: 128 pixels x 256 channels, K = 2304. 512 threads / 16 warps (4m x 4n).
// EPI==0: A = im2col(x), LDG prefetch + STS 2-stage; B cp.async 8-stage
// EPI==1: A & B pure cp.async copies, both 8-stage rings
template <int EPI>
__global__ __launch_bounds__(512, 1) void mma_kernel(
    const float* __restrict__ x,
    const float* __restrict__ ba,
    const float* __restrict__ bb,
    float* __restrict__ Cout)
{
    extern __shared__ __align__(16) char smem[];
    const uint32_t sb = smem_u32(smem);
    const int tid  = threadIdx.x;
    const int lane = tid & 31;
    const int wid  = tid >> 5;
    const int wm   = wid & 3;      // warp m-index (x32)
    const int wn   = wid >> 2;     // warp n-index (x64)
    const int m0   = blockIdx.x * 128;
    const int b    = m0 >> 12;

    // EPI0 producer mapping: (m, word w) for m and m+64
    const int pm = tid >> 3;       // 0..63
    const int pw = tid & 7;        // word 0..7 (k = c*16 + pw*2)

    // EPI1 A-copy mapping: (plane, k-row, 16B seg)
    const int cs  = tid & 15;            // seg
    const int ckl = (tid >> 4) & 15;     // k-row
    const int cpl = tid >> 8;            // 0 hi, 1 lo

    // ---- ldmatrix per-lane offsets (relative to stage bases) ----
    int offAh[2], offBh[4];
    if (EPI == 0) {
        const int rA   = lane & 15;
        const int segA = lane >> 4;
#pragma unroll
        for (int mt = 0; mt < 2; mt++) {
            int row = wm * 32 + mt * 16 + rA;
            offAh[mt] = row * 32 + (((segA * 4) ^ (rA & 4)) << 2);
        }
    } else {
        const int kr = (lane & 7) + ((lane & 16) ? 8 : 0);
        const int mo = (lane & 8) ? 1 : 0;
#pragma unroll
        for (int mt = 0; mt < 2; mt++) {
            int mseg = wm * 4 + mt * 2 + mo;
            offAh[mt] = kr * 256 + ((mseg ^ (kr & 7)) << 4);
        }
    }
    {
        const int rB   = (lane & 7) + ((lane & 16) ? 8 : 0);
        const int segB = (lane >> 3) & 1;
#pragma unroll
        for (int ntp = 0; ntp < 4; ntp++) {
            int row = wn * 64 + ntp * 16 + rB;
            offBh[ntp] = row * 32 + (((segB * 4) ^ (rB & 4)) << 2);
        }
    }

    // B-copy mapping
    const int bn = tid >> 1;
    const int bq = tid & 1;
    const int bdw = (bn * 8 + ((bq * 4) ^ (bn & 4))) * 4;  // byte offset in plane

    float cr[2][8][4];
#pragma unroll
    for (int mt = 0; mt < 2; mt++)
#pragma unroll
        for (int nt = 0; nt < 8; nt++)
#pragma unroll
            for (int j = 0; j < 4; j++) cr[mt][nt][j] = 0.f;

    const uint32_t* __restrict__ Bh = g_Bw[EPI][0];
    const uint32_t* __restrict__ Bl = g_Bw[EPI][1];

    // ---- async producers ----
    auto cpB = [&](int c) {
        if (c < NCH) {
            uint32_t dst = sb + (c & 7) * B_STG_B + bdw;
            const uint32_t* sh = &Bh[bn * KW + c * 8 + bq * 4];
            const uint32_t* sl = &Bl[bn * KW + c * 8 + bq * 4];
            cpasync16(dst, sh);
            cpasync16(dst + 8192, sl);
            if (EPI == 1) {
                uint32_t adst = sb + A_BASE + (c & 7) * A_STG_B + cpl * 4096
                              + ckl * 256 + ((cs ^ (ckl & 7)) << 4);
                const uint16_t* src = (cpl ? g_Al : g_Ah)
                    + (size_t)(c * 16 + ckl) * NPIX + m0 + cs * 8;
                cpasync16(adst, src);
            }
        }
        CP_COMMIT();
    };

    // EPI0 split producer: LDG phase (issued before MMAs), STS phase (after)
    auto ldgA = [&](int c, float pv[2][2]) {
        if (EPI != 0 || c >= NCH) return;
#pragma unroll
        for (int half = 0; half < 2; half++) {
            const int mg = m0 + pm + half * 64;
            const int hh = (mg & 4095) >> 6;
            const int ww = mg & 63;
            const int k  = c * 16 + pw * 2;
#pragma unroll
            for (int u = 0; u < 2; u++) {
                int kk  = k + u;
                int ci  = kk / 9;
                int tap = kk - ci * 9;
                int dy = tap / 3 - 1, dx = tap - (tap / 3) * 3 - 1;
                int y = hh + dy, xx2 = ww + dx;
                pv[half][u] = ((unsigned)y < (unsigned)HH &&
                               (unsigned)xx2 < (unsigned)WW)
                    ? x[((size_t)(b * CC + ci) << 12) + (y << 6) + xx2] : 0.f;
            }
        }
    };
    auto stsA = [&](int c, float pv[2][2]) {
        if (EPI != 0 || c >= NCH) return;
        char* stp = smem + A_BASE + (c & 1) * A_STG_B;
#pragma unroll
        for (int half = 0; half < 2; half++) {
            const int m = pm + half * 64;
            uint16_t h0, l0, h1, l1;
            split_bf16(pv[half][0], h0, l0);
            split_bf16(pv[half][1], h1, l1);
            int dw = m * 8 + (pw ^ (m & 4));
            *(uint32_t*)(stp +        dw * 4) = (uint32_t)h0 | ((uint32_t)h1 << 16);
            *(uint32_t*)(stp + 4096 + dw * 4) = (uint32_t)l0 | ((uint32_t)l1 << 16);
        }
    };

    // ---- prologue: 7 async groups in flight; EPI0 computes+stores A(0) ----
    cpB(0); cpB(1); cpB(2); cpB(3); cpB(4); cpB(5); cpB(6);
    float pv[2][2];
    if (EPI == 0) { ldgA(0, pv); stsA(0, pv); }

    for (int c = 0; c < NCH; c++) {
        CP_WAIT6();               // stage c resident (<=6 groups pending)
        __syncthreads();          // + all warps done reading recycled stages

        ldgA(c + 1, pv);          // EPI0: issue gathers early (covered by MMAs)
        cpB(c + 7);

        // ---- consume stage c ----
        const uint32_t stbB = sb + (c & 7) * B_STG_B;
        const uint32_t stbA = sb + A_BASE
                            + ((EPI == 0) ? (c & 1) : (c & 7)) * A_STG_B;
        uint32_t ah[2][4], al[2][4];
#pragma unroll
        for (int mt = 0; mt < 2; mt++) {
            if (EPI == 0) {
                ldsm4(ah[mt], stbA + offAh[mt]);
                ldsm4(al[mt], stbA + offAh[mt] + 4096);
            } else {
                ldsm4t(ah[mt], stbA + offAh[mt]);
                ldsm4t(al[mt], stbA + offAh[mt] + 4096);
            }
        }
#pragma unroll
        for (int ntp = 0; ntp < 4; ntp++) {
            uint32_t bh[4], bl[4];
            ldsm4(bh, stbB + offBh[ntp]);
            ldsm4(bl, stbB + offBh[ntp] + 8192);
#pragma unroll
            for (int j = 0; j < 2; j++) {
                const int nt = ntp * 2 + j;
#pragma unroll
                for (int mt = 0; mt < 2; mt++) {
                    float* cc = cr[mt][nt];
                    mma16816(cc, ah[mt], bh[2 * j], bh[2 * j + 1]);
                    mma16816(cc, ah[mt], bl[2 * j], bl[2 * j + 1]);
                    mma16816(cc, al[mt], bh[2 * j], bh[2 * j + 1]);
                }
            }
        }

        stsA(c + 1, pv);          // EPI0: store after MMAs (latency hidden)
    }
    CP_WAIT0();

    // ---- epilogue ----
    const int eg = lane >> 2;
    const int et = lane & 3;
#pragma unroll
    for (int mt = 0; mt < 2; mt++) {
#pragma unroll
        for (int nt = 0; nt < 8; nt++) {
            const float* cc = cr[mt][nt];
            int mloc = wm * 32 + mt * 16 + eg;
            int co   = wn * 64 + nt * 8 + et * 2;
#pragma unroll
            for (int rr = 0; rr < 2; rr++) {
                int m = m0 + mloc + rr * 8;
#pragma unroll
                for (int cw = 0; cw < 2; cw++) {
                    int c2 = co + cw;
                    float v = cc[rr * 2 + cw];
                    if (EPI == 0) {
                        if (c2 < CO1) {
                            float bias = (c2 < 144) ? ba[c2] : bb[c2 - 144];
                            g_Y[(size_t)c2 * NPIX + m] = v + bias;
                        }
                    } else {
                        Cout[((size_t)(b * OO + c2) << 12) + (m & 4095)] = v + ba[c2];
                    }
                }
            }
        }
    }
}

// -------- softmax + offsets -> packed bilinear weights/indices ------------
__global__ __launch_bounds__(256) void offmask_kernel() {
    int n = blockIdx.x * 256 + threadIdx.x;
    int g = blockIdx.y;
    int hw = n & 4095;
    int h = hw >> 6, w = hw & 63;

    float lg[KKT];
    float mx = -1e30f;
#pragma unroll
    for (int kk = 0; kk < KKT; kk++) {
        lg[kk] = g_Y[(size_t)(144 + g * KKT + kk) * NPIX + n];
        mx = fmaxf(mx, lg[kk]);
    }
    float s = 0.f;
#pragma unroll
    for (int kk = 0; kk < KKT; kk++) { lg[kk] = __expf(lg[kk] - mx); s += lg[kk]; }
    float inv = 1.f / s;

#pragma unroll
    for (int kk = 0; kk < KKT; kk++) {
        float a  = lg[kk] * inv;
        float dy = g_Y[(size_t)(g * 18 + 2 * kk    ) * NPIX + n];
        float dx = g_Y[(size_t)(g * 18 + 2 * kk + 1) * NPIX + n];
        float py = (float)(h - 1 + kk / 3) + dy;
        float px = (float)(w - 1 + kk % 3) + dx;

        float y0f = floorf(py), x0f = floorf(px);
        float fy = py - y0f, fx = px - x0f;
        y0f = fminf(fmaxf(y0f, -2.f), 65.f);
        x0f = fminf(fmaxf(x0f, -2.f), 65.f);
        int y0 = (int)y0f, x0 = (int)x0f;

        bool vy0 = (unsigned)y0       < (unsigned)HH;
        bool vy1 = (unsigned)(y0 + 1) < (unsigned)HH;
        bool vx0 = (unsigned)x0       < (unsigned)WW;
        bool vx1 = (unsigned)(x0 + 1) < (unsigned)WW;

        float w00 = (vy0 && vx0) ? (1.f - fy) * (1.f - fx) * a : 0.f;
        float w01 = (vy0 && vx1) ? (1.f - fy) * fx * a : 0.f;
        float w10 = (vy1 && vx0) ? fy * (1.f - fx) * a : 0.f;
        float w11 = (vy1 && vx1) ? fy * fx * a : 0.f;

        int r0  = min(max(y0,     0), HH - 1);
        int r1  = min(max(y0 + 1, 0), HH - 1);
        int cc0 = min(max(x0,     0), WW - 1);
        int cc1 = min(max(x0 + 1, 0), WW - 1);
        int pack = r0 | (r1 << 6) | (cc0 << 12) | (cc1 << 18);

        size_t o = (size_t)(g * KKT + kk) * NPIX + n;
        g_wq[o]  = make_float4(w00, w01, w10, w11);
        g_idx[o] = pack;
    }
}

// -------- sampler: wq/idx once per (pixel,g,tap), loop cg, write planes ---
__global__ __launch_bounds__(256) void sample_kernel(const float* __restrict__ x) {
    int n  = blockIdx.x * 256 + threadIdx.x;
    int gk = blockIdx.y;               // 0..71
    int g = gk / KKT, tap = gk - g * KKT;
    int b = n >> 12;

    size_t sidx = (size_t)gk * NPIX + n;
    float4 wq = g_wq[sidx];
    int pk = g_idx[sidx];
    int r0 = pk & 63, r1 = (pk >> 6) & 63;
    int c0 = (pk >> 12) & 63, c1 = (pk >> 18) & 63;
    int o00 = (r0 << 6) + c0, o01 = (r0 << 6) + c1;
    int o10 = (r1 << 6) + c0, o11 = (r1 << 6) + c1;

    const float* xb = x + ((size_t)(b * CC + g * CGR) << 12);
    const int kbase = g * 288 + tap;
#pragma unroll 4
    for (int cg = 0; cg < CGR; cg++) {
        const float* p = xb + ((size_t)cg << 12);
        float v = wq.x * p[o00] + wq.y * p[o01] + wq.z * p[o10] + wq.w * p[o11];
        uint16_t h, l;
        split_bf16(v, h, l);
        size_t a = (size_t)(kbase + cg * 9) * NPIX + n;
        g_Ah[a] = h;
        g_Al[a] = l;
    }
}

// --------------------------------------------------------------------------
extern "C" void kernel_launch(void* const* d_in, const int* in_sizes, int n_in,
                              void* d_out, int out_size) {
    const float* x      = nullptr;
    const float* w_off  = nullptr;
    const float* b_off  = nullptr;
    const float* w_attn = nullptr;
    const float* b_attn = nullptr;
    const float* w_out  = nullptr;
    const float* b_out  = nullptr;
    for (int i = 0; i < n_in; i++) {
        const float* p = (const float*)d_in[i];
        switch (in_sizes[i]) {
            case 8388608: x      = p; break;
            case 331776:  w_off  = p; break;
            case 144:     b_off  = p; break;
            case 165888:  w_attn = p; break;
            case 72:      b_attn = p; break;
            case 589824:  w_out  = p; break;
            case 256:     b_out  = p; break;
            default: break;
        }
    }
    if (!x || !w_off || !b_off || !w_attn || !b_attn || !w_out || !b_out)
        return;
    float* out = (float*)d_out;

    cudaFuncSetAttribute(mma_kernel<0>,
        cudaFuncAttributeMaxDynamicSharedMemorySize, SMEM_TOT);
    cudaFuncSetAttribute(mma_kernel<1>,
        cudaFuncAttributeMaxDynamicSharedMemorySize, SMEM_TOT);

    // 0) stage weights: fp32 -> bf16 hi/lo packed word pairs
    stageB_kernel<<<(2 * 256 * KW) / 256, 256>>>(w_off, w_attn, w_out);

    // 1) offset/mask conv (HMMA, fused im2col, deep cp.async B) -> g_Y
    mma_kernel<0><<<NPIX / 128, 512, SMEM_TOT>>>(x, b_off, b_attn, nullptr);

    // 2) softmax + packed bilinear weights/indices
    offmask_kernel<<<dim3(NPIX / 256, GG), 256>>>();

    // 3) sampling pass: modulated bilinear gather -> bf16 hi/lo planes
    sample_kernel<<<dim3(NPIX / 256, GG * KKT), 256>>>(x);

    // 4) deformable conv (HMMA, A/B cp.async 8-stage) -> NCHW out
    mma_kernel<1><<<NPIX / 128, 512, SMEM_TOT>>>(x, b_out, nullptr, out);
}

// round 11
// speedup vs baseline: 1.9215x; 1.4198x over previous
#include <cuda_runtime.h>
#include <cuda_fp16.h>
#include <cstdint>
#include <cstddef>

#define BB 8
#define CC 256
#define HH 64
#define WW 64
#define GG 8
#define CGR 32
#define KKT 9
#define OO 256
#define NPIX (BB*HH*WW)        // 32768
#define KC (CC*KKT)            // 2304
#define KW (KC/2)              // 1152 b32 words per row
#define CO1 216
#define HWSZ (HH*WW)           // 4096
#define NCH (KC/16)            // 144 k16 steps

// smem rings: B 8 stages x 8KB (hi only); A 8 stages x 8KB (hi 4K | lo 4K)
#define B_STG_B 8192
#define A_BASE  65536
#define A_STG_B 8192
#define SMEM_TOT (A_BASE + 8*A_STG_B)   // 131072

// -------- scratch (static device globals) ---------------------------------
__device__ __align__(16) float    g_Y[(size_t)CO1 * NPIX];          // conv1 out
__device__ __align__(16) float4   g_wq[(size_t)(GG*KKT) * NPIX];    // bilinear wts * attn
__device__ __align__(16) int      g_idx[(size_t)(GG*KKT) * NPIX];   // packed indices
__device__ __align__(16) uint32_t g_Bw[2][256 * KW];                // weights hi fp16
__device__ __align__(16) uint16_t g_Ah[(size_t)KC * NPIX];          // sampled A hi plane
__device__ __align__(16) uint16_t g_Al[(size_t)KC * NPIX];          // sampled A lo plane

// -------- helpers ---------------------------------------------------------
__device__ __forceinline__ uint32_t smem_u32(const void* p) {
    uint32_t a;
    asm("{ .reg .u64 t; cvta.to.shared.u64 t, %1; cvt.u32.u64 %0, t; }"
        : "=r"(a) : "l"(p));
    return a;
}
__device__ __forceinline__ void cpasync16(uint32_t dst, const void* src) {
    asm volatile("cp.async.cg.shared.global [%0], [%1], 16;"
        :: "r"(dst), "l"(src) : "memory");
}
#define CP_COMMIT() asm volatile("cp.async.commit_group;" ::: "memory")
#define CP_WAIT6()  asm volatile("cp.async.wait_group 6;" ::: "memory")
#define CP_WAIT0()  asm volatile("cp.async.wait_group 0;" ::: "memory")
__device__ __forceinline__ void ldsm4(uint32_t* r, uint32_t addr) {
    asm volatile("ldmatrix.sync.aligned.m8n8.x4.shared.b16 {%0,%1,%2,%3}, [%4];"
        : "=r"(r[0]), "=r"(r[1]), "=r"(r[2]), "=r"(r[3]) : "r"(addr));
}
__device__ __forceinline__ void ldsm4t(uint32_t* r, uint32_t addr) {
    asm volatile("ldmatrix.sync.aligned.m8n8.x4.trans.shared.b16 {%0,%1,%2,%3}, [%4];"
        : "=r"(r[0]), "=r"(r[1]), "=r"(r[2]), "=r"(r[3]) : "r"(addr));
}
__device__ __forceinline__ void mma16816(float* c, const uint32_t* a,
                                         uint32_t b0, uint32_t b1) {
    asm volatile(
        "mma.sync.aligned.m16n8k16.row.col.f32.f16.f16.f32 "
        "{%0,%1,%2,%3}, {%4,%5,%6,%7}, {%8,%9}, {%0,%1,%2,%3};"
        : "+f"(c[0]), "+f"(c[1]), "+f"(c[2]), "+f"(c[3])
        : "r"(a[0]), "r"(a[1]), "r"(a[2]), "r"(a[3]), "r"(b0), "r"(b1));
}
__device__ __forceinline__ void split_fp16(float v, uint16_t& h, uint16_t& l) {
    __half hb = __float2half_rn(v);
    float r = v - __half2float(hb);
    __half lb = __float2half_rn(r);
    h = *reinterpret_cast<uint16_t*>(&hb);
    l = *reinterpret_cast<uint16_t*>(&lb);
}
__device__ __forceinline__ uint16_t to_fp16(float v) {
    __half hb = __float2half_rn(v);
    return *reinterpret_cast<uint16_t*>(&hb);
}

// -------- setup: weights -> fp16 hi plane word pairs ----------------------
__global__ __launch_bounds__(256) void stageB_kernel(
    const float* __restrict__ w_off, const float* __restrict__ w_attn,
    const float* __restrict__ w_out)
{
    int idx = blockIdx.x * 256 + threadIdx.x;     // over 2*256*1152
    int gemm = idx / (256 * KW);
    int rem  = idx - gemm * (256 * KW);
    int row  = rem / KW;
    int wd   = rem - row * KW;
    int k    = wd * 2;
    float v0 = 0.f, v1 = 0.f;
    if (gemm == 0) {
        if (row < 144) {
            v0 = w_off[(size_t)row * KC + k];
            v1 = w_off[(size_t)row * KC + k + 1];
        } else if (row < CO1) {
            v0 = w_attn[(size_t)(row - 144) * KC + k];
            v1 = w_attn[(size_t)(row - 144) * KC + k + 1];
        }
    } else {
        v0 = w_out[(size_t)row * KC + k];
        v1 = w_out[(size_t)row * KC + k + 1];
    }
    g_Bw[gemm][row * KW + wd] =
        (uint32_t)to_fp16(v0) | ((uint32_t)to_fp16(v1) << 16);
}

// -------- main warp-MMA implicit GEMM -------------------------------------
// CTA: 128 pixels x 256 channels, K = 2304. 512 threads / 16 warps (4m x 4n).
// A split fp16 (hi+lo), B single fp16: C = Ah*B + Al*B (error ~2^-12).
// EPI==0: A = im2col(x), LDG prefetch + STS 2-stage; B cp.async 8-stage
// EPI==1: A & B pure cp.async copies, both 8-stage rings
template <int EPI>
__global__ __launch_bounds__(512, 1) void mma_kernel(
    const float* __restrict__ x,
    const float* __restrict__ ba,
    const float* __restrict__ bb,
    float* __restrict__ Cout)
{
    extern __shared__ __align__(16) char smem[];
    const uint32_t sb = smem_u32(smem);
    const int tid  = threadIdx.x;
    const int lane = tid & 31;
    const int wid  = tid >> 5;
    const int wm   = wid & 3;      // warp m-index (x32)
    const int wn   = wid >> 2;     // warp n-index (x64)
    const int m0   = blockIdx.x * 128;
    const int b    = m0 >> 12;

    // EPI0 producer mapping: (m, word w) for m and m+64
    const int pm = tid >> 3;       // 0..63
    const int pw = tid & 7;        // word 0..7 (k = c*16 + pw*2)

    // EPI1 A-copy mapping: (plane, k-row, 16B seg)
    const int cs  = tid & 15;            // seg
    const int ckl = (tid >> 4) & 15;     // k-row
    const int cpl = tid >> 8;            // 0 hi, 1 lo

    // ---- ldmatrix per-lane offsets (relative to stage bases) ----
    int offAh[2], offBh[4];
    if (EPI == 0) {
        const int rA   = lane & 15;
        const int segA = lane >> 4;
#pragma unroll
        for (int mt = 0; mt < 2; mt++) {
            int row = wm * 32 + mt * 16 + rA;
            offAh[mt] = row * 32 + (((segA * 4) ^ (rA & 4)) << 2);
        }
    } else {
        const int kr = (lane & 7) + ((lane & 16) ? 8 : 0);
        const int mo = (lane & 8) ? 1 : 0;
#pragma unroll
        for (int mt = 0; mt < 2; mt++) {
            int mseg = wm * 4 + mt * 2 + mo;
            offAh[mt] = kr * 256 + ((mseg ^ (kr & 7)) << 4);
        }
    }
    {
        const int rB   = (lane & 7) + ((lane & 16) ? 8 : 0);
        const int segB = (lane >> 3) & 1;
#pragma unroll
        for (int ntp = 0; ntp < 4; ntp++) {
            int row = wn * 64 + ntp * 16 + rB;
            offBh[ntp] = row * 32 + (((segB * 4) ^ (rB & 4)) << 2);
        }
    }

    // B-copy mapping: 512 threads x 16B = full 8KB hi plane
    const int bn = tid >> 1;
    const int bq = tid & 1;
    const int bdw = (bn * 8 + ((bq * 4) ^ (bn & 4))) * 4;  // byte offset in plane

    float cr[2][8][4];
#pragma unroll
    for (int mt = 0; mt < 2; mt++)
#pragma unroll
        for (int nt = 0; nt < 8; nt++)
#pragma unroll
            for (int j = 0; j < 4; j++) cr[mt][nt][j] = 0.f;

    const uint32_t* __restrict__ Bh = g_Bw[EPI];

    // ---- async producers ----
    auto cpB = [&](int c) {
        if (c < NCH) {
            uint32_t dst = sb + (c & 7) * B_STG_B + bdw;
            cpasync16(dst, &Bh[bn * KW + c * 8 + bq * 4]);
            if (EPI == 1) {
                uint32_t adst = sb + A_BASE + (c & 7) * A_STG_B + cpl * 4096
                              + ckl * 256 + ((cs ^ (ckl & 7)) << 4);
                const uint16_t* src = (cpl ? g_Al : g_Ah)
                    + (size_t)(c * 16 + ckl) * NPIX + m0 + cs * 8;
                cpasync16(adst, src);
            }
        }
        CP_COMMIT();
    };

    // EPI0 split producer: LDG phase (issued before MMAs), STS phase (after)
    auto ldgA = [&](int c, float pv[2][2]) {
        if (EPI != 0 || c >= NCH) return;
#pragma unroll
        for (int half = 0; half < 2; half++) {
            const int mg = m0 + pm + half * 64;
            const int hh = (mg & 4095) >> 6;
            const int ww = mg & 63;
            const int k  = c * 16 + pw * 2;
#pragma unroll
            for (int u = 0; u < 2; u++) {
                int kk  = k + u;
                int ci  = kk / 9;
                int tap = kk - ci * 9;
                int dy = tap / 3 - 1, dx = tap - (tap / 3) * 3 - 1;
                int y = hh + dy, xx2 = ww + dx;
                pv[half][u] = ((unsigned)y < (unsigned)HH &&
                               (unsigned)xx2 < (unsigned)WW)
                    ? x[((size_t)(b * CC + ci) << 12) + (y << 6) + xx2] : 0.f;
            }
        }
    };
    auto stsA = [&](int c, float pv[2][2]) {
        if (EPI != 0 || c >= NCH) return;
        char* stp = smem + A_BASE + (c & 1) * A_STG_B;
#pragma unroll
        for (int half = 0; half < 2; half++) {
            const int m = pm + half * 64;
            uint16_t h0, l0, h1, l1;
            split_fp16(pv[half][0], h0, l0);
            split_fp16(pv[half][1], h1, l1);
            int dw = m * 8 + (pw ^ (m & 4));
            *(uint32_t*)(stp +        dw * 4) = (uint32_t)h0 | ((uint32_t)h1 << 16);
            *(uint32_t*)(stp + 4096 + dw * 4) = (uint32_t)l0 | ((uint32_t)l1 << 16);
        }
    };

    // ---- prologue: 7 async groups in flight; EPI0 computes+stores A(0) ----
    cpB(0); cpB(1); cpB(2); cpB(3); cpB(4); cpB(5); cpB(6);
    float pv[2][2];
    if (EPI == 0) { ldgA(0, pv); stsA(0, pv); }

    for (int c = 0; c < NCH; c++) {
        CP_WAIT6();               // stage c resident (<=6 groups pending)
        __syncthreads();          // + all warps done reading recycled stages

        ldgA(c + 1, pv);          // EPI0: issue gathers early (covered by MMAs)
        cpB(c + 7);

        // ---- consume stage c ----
        const uint32_t stbB = sb + (c & 7) * B_STG_B;
        const uint32_t stbA = sb + A_BASE
                            + ((EPI == 0) ? (c & 1) : (c & 7)) * A_STG_B;
        uint32_t ah[2][4], al[2][4];
#pragma unroll
        for (int mt = 0; mt < 2; mt++) {
            if (EPI == 0) {
                ldsm4(ah[mt], stbA + offAh[mt]);
                ldsm4(al[mt], stbA + offAh[mt] + 4096);
            } else {
                ldsm4t(ah[mt], stbA + offAh[mt]);
                ldsm4t(al[mt], stbA + offAh[mt] + 4096);
            }
        }
#pragma unroll
        for (int ntp = 0; ntp < 4; ntp++) {
            // GEMM0: channels >= 216 are zero padding -> skip (warp-uniform)
            if (EPI == 0 && wn * 64 + ntp * 16 >= CO1) continue;
            uint32_t bh[4];
            ldsm4(bh, stbB + offBh[ntp]);
#pragma unroll
            for (int j = 0; j < 2; j++) {
                const int nt = ntp * 2 + j;
                if (EPI == 0 && wn * 64 + ntp * 16 + j * 8 >= CO1) continue;
#pragma unroll
                for (int mt = 0; mt < 2; mt++) {
                    float* cc = cr[mt][nt];
                    mma16816(cc, ah[mt], bh[2 * j], bh[2 * j + 1]);
                    mma16816(cc, al[mt], bh[2 * j], bh[2 * j + 1]);
                }
            }
        }

        stsA(c + 1, pv);          // EPI0: store after MMAs (latency hidden)
    }
    CP_WAIT0();

    // ---- epilogue ----
    const int eg = lane >> 2;
    const int et = lane & 3;
#pragma unroll
    for (int mt = 0; mt < 2; mt++) {
#pragma unroll
        for (int nt = 0; nt < 8; nt++) {
            const float* cc = cr[mt][nt];
            int mloc = wm * 32 + mt * 16 + eg;
            int co   = wn * 64 + nt * 8 + et * 2;
#pragma unroll
            for (int rr = 0; rr < 2; rr++) {
                int m = m0 + mloc + rr * 8;
#pragma unroll
                for (int cw = 0; cw < 2; cw++) {
                    int c2 = co + cw;
                    float v = cc[rr * 2 + cw];
                    if (EPI == 0) {
                        if (c2 < CO1) {
                            float bias = (c2 < 144) ? ba[c2] : bb[c2 - 144];
                            g_Y[(size_t)c2 * NPIX + m] = v + bias;
                        }
                    } else {
                        Cout[((size_t)(b * OO + c2) << 12) + (m & 4095)] = v + ba[c2];
                    }
                }
            }
        }
    }
}

// -------- softmax + offsets -> packed bilinear weights/indices ------------
__global__ __launch_bounds__(256) void offmask_kernel() {
    int n = blockIdx.x * 256 + threadIdx.x;
    int g = blockIdx.y;
    int hw = n & 4095;
    int h = hw >> 6, w = hw & 63;

    float lg[KKT];
    float mx = -1e30f;
#pragma unroll
    for (int kk = 0; kk < KKT; kk++) {
        lg[kk] = g_Y[(size_t)(144 + g * KKT + kk) * NPIX + n];
        mx = fmaxf(mx, lg[kk]);
    }
    float s = 0.f;
#pragma unroll
    for (int kk = 0; kk < KKT; kk++) { lg[kk] = __expf(lg[kk] - mx); s += lg[kk]; }
    float inv = 1.f / s;

#pragma unroll
    for (int kk = 0; kk < KKT; kk++) {
        float a  = lg[kk] * inv;
        float dy = g_Y[(size_t)(g * 18 + 2 * kk    ) * NPIX + n];
        float dx = g_Y[(size_t)(g * 18 + 2 * kk + 1) * NPIX + n];
        float py = (float)(h - 1 + kk / 3) + dy;
        float px = (float)(w - 1 + kk % 3) + dx;

        float y0f = floorf(py), x0f = floorf(px);
        float fy = py - y0f, fx = px - x0f;
        y0f = fminf(fmaxf(y0f, -2.f), 65.f);
        x0f = fminf(fmaxf(x0f, -2.f), 65.f);
        int y0 = (int)y0f, x0 = (int)x0f;

        bool vy0 = (unsigned)y0       < (unsigned)HH;
        bool vy1 = (unsigned)(y0 + 1) < (unsigned)HH;
        bool vx0 = (unsigned)x0       < (unsigned)WW;
        bool vx1 = (unsigned)(x0 + 1) < (unsigned)WW;

        float w00 = (vy0 && vx0) ? (1.f - fy) * (1.f - fx) * a : 0.f;
        float w01 = (vy0 && vx1) ? (1.f - fy) * fx * a : 0.f;
        float w10 = (vy1 && vx0) ? fy * (1.f - fx) * a : 0.f;
        float w11 = (vy1 && vx1) ? fy * fx * a : 0.f;

        int r0  = min(max(y0,     0), HH - 1);
        int r1  = min(max(y0 + 1, 0), HH - 1);
        int cc0 = min(max(x0,     0), WW - 1);
        int cc1 = min(max(x0 + 1, 0), WW - 1);
        int pack = r0 | (r1 << 6) | (cc0 << 12) | (cc1 << 18);

        size_t o = (size_t)(g * KKT + kk) * NPIX + n;
        g_wq[o]  = make_float4(w00, w01, w10, w11);
        g_idx[o] = pack;
    }
}

// -------- sampler: wq/idx once per (pixel,g,tap), loop cg, write planes ---
__global__ __launch_bounds__(256) void sample_kernel(const float* __restrict__ x) {
    int n  = blockIdx.x * 256 + threadIdx.x;
    int gk = blockIdx.y;               // 0..71
    int g = gk / KKT, tap = gk - g * KKT;
    int b = n >> 12;

    size_t sidx = (size_t)gk * NPIX + n;
    float4 wq = g_wq[sidx];
    int pk = g_idx[sidx];
    int r0 = pk & 63, r1 = (pk >> 6) & 63;
    int c0 = (pk >> 12) & 63, c1 = (pk >> 18) & 63;
    int o00 = (r0 << 6) + c0, o01 = (r0 << 6) + c1;
    int o10 = (r1 << 6) + c0, o11 = (r1 << 6) + c1;

    const float* xb = x + ((size_t)(b * CC + g * CGR) << 12);
    const int kbase = g * 288 + tap;
#pragma unroll 4
    for (int cg = 0; cg < CGR; cg++) {
        const float* p = xb + ((size_t)cg << 12);
        float v = wq.x * p[o00] + wq.y * p[o01] + wq.z * p[o10] + wq.w * p[o11];
        uint16_t h, l;
        split_fp16(v, h, l);
        size_t a = (size_t)(kbase + cg * 9) * NPIX + n;
        g_Ah[a] = h;
        g_Al[a] = l;
    }
}

// --------------------------------------------------------------------------
extern "C" void kernel_launch(void* const* d_in, const int* in_sizes, int n_in,
                              void* d_out, int out_size) {
    const float* x      = nullptr;
    const float* w_off  = nullptr;
    const float* b_off  = nullptr;
    const float* w_attn = nullptr;
    const float* b_attn = nullptr;
    const float* w_out  = nullptr;
    const float* b_out  = nullptr;
    for (int i = 0; i < n_in; i++) {
        const float* p = (const float*)d_in[i];
        switch (in_sizes[i]) {
            case 8388608: x      = p; break;
            case 331776:  w_off  = p; break;
            case 144:     b_off  = p; break;
            case 165888:  w_attn = p; break;
            case 72:      b_attn = p; break;
            case 589824:  w_out  = p; break;
            case 256:     b_out  = p; break;
            default: break;
        }
    }
    if (!x || !w_off || !b_off || !w_attn || !b_attn || !w_out || !b_out)
        return;
    float* out = (float*)d_out;

    cudaFuncSetAttribute(mma_kernel<0>,
        cudaFuncAttributeMaxDynamicSharedMemorySize, SMEM_TOT);
    cudaFuncSetAttribute(mma_kernel<1>,
        cudaFuncAttributeMaxDynamicSharedMemorySize, SMEM_TOT);

    // 0) stage weights: fp32 -> fp16 hi plane word pairs
    stageB_kernel<<<(2 * 256 * KW) / 256, 256>>>(w_off, w_attn, w_out);

    // 1) offset/mask conv (HMMA, fused im2col, deep cp.async B) -> g_Y
    mma_kernel<0><<<NPIX / 128, 512, SMEM_TOT>>>(x, b_off, b_attn, nullptr);

    // 2) softmax + packed bilinear weights/indices
    offmask_kernel<<<dim3(NPIX / 256, GG), 256>>>();

    // 3) sampling pass: modulated bilinear gather -> fp16 hi/lo planes
    sample_kernel<<<dim3(NPIX / 256, GG * KKT), 256>>>(x);

    // 4) deformable conv (HMMA, A/B cp.async 8-stage) -> NCHW out
    mma_kernel<1><<<NPIX / 128, 512, SMEM_TOT>>>(x, b_out, nullptr, out);
}

// round 12
// speedup vs baseline: 1.9835x; 1.0323x over previous
#include <cuda_runtime.h>
#include <cuda_fp16.h>
#include <cstdint>
#include <cstddef>

#define BB 8
#define CC 256
#define HH 64
#define WW 64
#define GG 8
#define CGR 32
#define KKT 9
#define OO 256
#define NPIX (BB*HH*WW)        // 32768
#define KC (CC*KKT)            // 2304
#define KW (KC/2)              // 1152 b32 words per row
#define CO1 216
#define HWSZ (HH*WW)           // 4096
#define NCH (KC/16)            // 144 k16 steps

// smem rings: B 8 stages x 8KB (hi only); A 8 stages x 8KB (hi 4K | lo 4K)
#define B_STG_B 8192
#define A_BASE  65536
#define A_STG_B 8192
#define SMEM_TOT (A_BASE + 8*A_STG_B)   // 131072

// -------- scratch (static device globals) ---------------------------------
__device__ __align__(16) float    g_Y[(size_t)CO1 * NPIX];          // conv1 out
__device__ __align__(16) float4   g_wq[(size_t)(GG*KKT) * NPIX];    // bilinear wts * attn
__device__ __align__(16) int      g_idx[(size_t)(GG*KKT) * NPIX];   // packed indices
__device__ __align__(16) uint32_t g_Bw[2][256 * KW];                // weights hi fp16
__device__ __align__(16) uint16_t g_Ah[(size_t)KC * NPIX];          // sampled A hi plane
__device__ __align__(16) uint16_t g_Al[(size_t)KC * NPIX];          // sampled A lo plane

// -------- helpers ---------------------------------------------------------
__device__ __forceinline__ uint32_t smem_u32(const void* p) {
    uint32_t a;
    asm("{ .reg .u64 t; cvta.to.shared.u64 t, %1; cvt.u32.u64 %0, t; }"
        : "=r"(a) : "l"(p));
    return a;
}
__device__ __forceinline__ void cpasync16(uint32_t dst, const void* src) {
    asm volatile("cp.async.cg.shared.global [%0], [%1], 16;"
        :: "r"(dst), "l"(src) : "memory");
}
#define CP_COMMIT() asm volatile("cp.async.commit_group;" ::: "memory")
#define CP_WAIT6()  asm volatile("cp.async.wait_group 6;" ::: "memory")
#define CP_WAIT0()  asm volatile("cp.async.wait_group 0;" ::: "memory")
__device__ __forceinline__ void ldsm4(uint32_t* r, uint32_t addr) {
    asm volatile("ldmatrix.sync.aligned.m8n8.x4.shared.b16 {%0,%1,%2,%3}, [%4];"
        : "=r"(r[0]), "=r"(r[1]), "=r"(r[2]), "=r"(r[3]) : "r"(addr));
}
__device__ __forceinline__ void ldsm4t(uint32_t* r, uint32_t addr) {
    asm volatile("ldmatrix.sync.aligned.m8n8.x4.trans.shared.b16 {%0,%1,%2,%3}, [%4];"
        : "=r"(r[0]), "=r"(r[1]), "=r"(r[2]), "=r"(r[3]) : "r"(addr));
}
__device__ __forceinline__ void mma16816(float* c, const uint32_t* a,
                                         uint32_t b0, uint32_t b1) {
    asm volatile(
        "mma.sync.aligned.m16n8k16.row.col.f32.f16.f16.f32 "
        "{%0,%1,%2,%3}, {%4,%5,%6,%7}, {%8,%9}, {%0,%1,%2,%3};"
        : "+f"(c[0]), "+f"(c[1]), "+f"(c[2]), "+f"(c[3])
        : "r"(a[0]), "r"(a[1]), "r"(a[2]), "r"(a[3]), "r"(b0), "r"(b1));
}
__device__ __forceinline__ void split_fp16(float v, uint16_t& h, uint16_t& l) {
    __half hb = __float2half_rn(v);
    float r = v - __half2float(hb);
    __half lb = __float2half_rn(r);
    h = *reinterpret_cast<uint16_t*>(&hb);
    l = *reinterpret_cast<uint16_t*>(&lb);
}
__device__ __forceinline__ uint16_t to_fp16(float v) {
    __half hb = __float2half_rn(v);
    return *reinterpret_cast<uint16_t*>(&hb);
}

// -------- setup: weights -> fp16 hi plane word pairs ----------------------
__global__ __launch_bounds__(256) void stageB_kernel(
    const float* __restrict__ w_off, const float* __restrict__ w_attn,
    const float* __restrict__ w_out)
{
    int idx = blockIdx.x * 256 + threadIdx.x;     // over 2*256*1152
    int gemm = idx / (256 * KW);
    int rem  = idx - gemm * (256 * KW);
    int row  = rem / KW;
    int wd   = rem - row * KW;
    int k    = wd * 2;
    float v0 = 0.f, v1 = 0.f;
    if (gemm == 0) {
        if (row < 144) {
            v0 = w_off[(size_t)row * KC + k];
            v1 = w_off[(size_t)row * KC + k + 1];
        } else if (row < CO1) {
            v0 = w_attn[(size_t)(row - 144) * KC + k];
            v1 = w_attn[(size_t)(row - 144) * KC + k + 1];
        }
    } else {
        v0 = w_out[(size_t)row * KC + k];
        v1 = w_out[(size_t)row * KC + k + 1];
    }
    g_Bw[gemm][row * KW + wd] =
        (uint32_t)to_fp16(v0) | ((uint32_t)to_fp16(v1) << 16);
}

// -------- main warp-MMA implicit GEMM -------------------------------------
// CTA: 128 pixels x 256 channels, K = 2304. 512 threads / 16 warps (4m x 4n).
// EPI==0: 1-term (Ah*Bh): conv1 logits tolerate 2^-11; fused im2col producer
// EPI==1: 2-term (Ah*Bh + Al*Bh): output path, error ~2^-12; pure cp.async
template <int EPI>
__global__ __launch_bounds__(512, 1) void mma_kernel(
    const float* __restrict__ x,
    const float* __restrict__ ba,
    const float* __restrict__ bb,
    float* __restrict__ Cout)
{
    extern __shared__ __align__(16) char smem[];
    const uint32_t sb = smem_u32(smem);
    const int tid  = threadIdx.x;
    const int lane = tid & 31;
    const int wid  = tid >> 5;
    const int wm   = wid & 3;      // warp m-index (x32)
    const int wn   = wid >> 2;     // warp n-index (x64)
    const int m0   = blockIdx.x * 128;
    const int b    = m0 >> 12;

    // EPI0 producer mapping: (m, word w) for m and m+64
    const int pm = tid >> 3;       // 0..63
    const int pw = tid & 7;        // word 0..7 (k = c*16 + pw*2)

    // EPI1 A-copy mapping: (plane, k-row, 16B seg)
    const int cs  = tid & 15;            // seg
    const int ckl = (tid >> 4) & 15;     // k-row
    const int cpl = tid >> 8;            // 0 hi, 1 lo

    // ---- ldmatrix per-lane offsets (relative to stage bases) ----
    int offAh[2], offBh[4];
    if (EPI == 0) {
        const int rA   = lane & 15;
        const int segA = lane >> 4;
#pragma unroll
        for (int mt = 0; mt < 2; mt++) {
            int row = wm * 32 + mt * 16 + rA;
            offAh[mt] = row * 32 + (((segA * 4) ^ (rA & 4)) << 2);
        }
    } else {
        const int kr = (lane & 7) + ((lane & 16) ? 8 : 0);
        const int mo = (lane & 8) ? 1 : 0;
#pragma unroll
        for (int mt = 0; mt < 2; mt++) {
            int mseg = wm * 4 + mt * 2 + mo;
            offAh[mt] = kr * 256 + ((mseg ^ (kr & 7)) << 4);
        }
    }
    {
        const int rB   = (lane & 7) + ((lane & 16) ? 8 : 0);
        const int segB = (lane >> 3) & 1;
#pragma unroll
        for (int ntp = 0; ntp < 4; ntp++) {
            int row = wn * 64 + ntp * 16 + rB;
            offBh[ntp] = row * 32 + (((segB * 4) ^ (rB & 4)) << 2);
        }
    }

    // B-copy mapping: 512 threads x 16B = full 8KB hi plane
    const int bn = tid >> 1;
    const int bq = tid & 1;
    const int bdw = (bn * 8 + ((bq * 4) ^ (bn & 4))) * 4;  // byte offset in plane

    float cr[2][8][4];
#pragma unroll
    for (int mt = 0; mt < 2; mt++)
#pragma unroll
        for (int nt = 0; nt < 8; nt++)
#pragma unroll
            for (int j = 0; j < 4; j++) cr[mt][nt][j] = 0.f;

    const uint32_t* __restrict__ Bh = g_Bw[EPI];

    // ---- async producers ----
    auto cpB = [&](int c) {
        if (c < NCH) {
            uint32_t dst = sb + (c & 7) * B_STG_B + bdw;
            cpasync16(dst, &Bh[bn * KW + c * 8 + bq * 4]);
            if (EPI == 1) {
                uint32_t adst = sb + A_BASE + (c & 7) * A_STG_B + cpl * 4096
                              + ckl * 256 + ((cs ^ (ckl & 7)) << 4);
                const uint16_t* src = (cpl ? g_Al : g_Ah)
                    + (size_t)(c * 16 + ckl) * NPIX + m0 + cs * 8;
                cpasync16(adst, src);
            }
        }
        CP_COMMIT();
    };

    // EPI0 split producer: LDG phase (issued before MMAs), STS phase (after)
    auto ldgA = [&](int c, float pv[2][2]) {
        if (EPI != 0 || c >= NCH) return;
#pragma unroll
        for (int half = 0; half < 2; half++) {
            const int mg = m0 + pm + half * 64;
            const int hh = (mg & 4095) >> 6;
            const int ww = mg & 63;
            const int k  = c * 16 + pw * 2;
#pragma unroll
            for (int u = 0; u < 2; u++) {
                int kk  = k + u;
                int ci  = kk / 9;
                int tap = kk - ci * 9;
                int dy = tap / 3 - 1, dx = tap - (tap / 3) * 3 - 1;
                int y = hh + dy, xx2 = ww + dx;
                pv[half][u] = ((unsigned)y < (unsigned)HH &&
                               (unsigned)xx2 < (unsigned)WW)
                    ? x[((size_t)(b * CC + ci) << 12) + (y << 6) + xx2] : 0.f;
            }
        }
    };
    auto stsA = [&](int c, float pv[2][2]) {
        if (EPI != 0 || c >= NCH) return;
        char* stp = smem + A_BASE + (c & 1) * A_STG_B;
#pragma unroll
        for (int half = 0; half < 2; half++) {
            const int m = pm + half * 64;
            int dw = m * 8 + (pw ^ (m & 4));
            // 1-term GEMM0: hi plane only
            *(uint32_t*)(stp + dw * 4) =
                (uint32_t)to_fp16(pv[half][0]) |
                ((uint32_t)to_fp16(pv[half][1]) << 16);
        }
    };

    // ---- prologue: 7 async groups in flight; EPI0 computes+stores A(0) ----
    cpB(0); cpB(1); cpB(2); cpB(3); cpB(4); cpB(5); cpB(6);
    float pv[2][2];
    if (EPI == 0) { ldgA(0, pv); stsA(0, pv); }

    for (int c = 0; c < NCH; c++) {
        CP_WAIT6();               // stage c resident (<=6 groups pending)
        __syncthreads();          // + all warps done reading recycled stages

        ldgA(c + 1, pv);          // EPI0: issue gathers early (covered by MMAs)
        cpB(c + 7);

        // ---- consume stage c ----
        const uint32_t stbB = sb + (c & 7) * B_STG_B;
        const uint32_t stbA = sb + A_BASE
                            + ((EPI == 0) ? (c & 1) : (c & 7)) * A_STG_B;
        uint32_t ah[2][4], al[2][4];
#pragma unroll
        for (int mt = 0; mt < 2; mt++) {
            if (EPI == 0) {
                ldsm4(ah[mt], stbA + offAh[mt]);
            } else {
                ldsm4t(ah[mt], stbA + offAh[mt]);
                ldsm4t(al[mt], stbA + offAh[mt] + 4096);
            }
        }
#pragma unroll
        for (int ntp = 0; ntp < 4; ntp++) {
            // GEMM0: channels >= 216 are zero padding -> skip (warp-uniform)
            if (EPI == 0 && wn * 64 + ntp * 16 >= CO1) continue;
            uint32_t bh[4];
            ldsm4(bh, stbB + offBh[ntp]);
#pragma unroll
            for (int j = 0; j < 2; j++) {
                const int nt = ntp * 2 + j;
                if (EPI == 0 && wn * 64 + ntp * 16 + j * 8 >= CO1) continue;
#pragma unroll
                for (int mt = 0; mt < 2; mt++) {
                    float* cc = cr[mt][nt];
                    mma16816(cc, ah[mt], bh[2 * j], bh[2 * j + 1]);
                    if (EPI == 1)
                        mma16816(cc, al[mt], bh[2 * j], bh[2 * j + 1]);
                }
            }
        }

        stsA(c + 1, pv);          // EPI0: store after MMAs (latency hidden)
    }
    CP_WAIT0();

    // ---- epilogue ----
    const int eg = lane >> 2;
    const int et = lane & 3;
#pragma unroll
    for (int mt = 0; mt < 2; mt++) {
#pragma unroll
        for (int nt = 0; nt < 8; nt++) {
            const float* cc = cr[mt][nt];
            int mloc = wm * 32 + mt * 16 + eg;
            int co   = wn * 64 + nt * 8 + et * 2;
#pragma unroll
            for (int rr = 0; rr < 2; rr++) {
                int m = m0 + mloc + rr * 8;
#pragma unroll
                for (int cw = 0; cw < 2; cw++) {
                    int c2 = co + cw;
                    float v = cc[rr * 2 + cw];
                    if (EPI == 0) {
                        if (c2 < CO1) {
                            float bias = (c2 < 144) ? ba[c2] : bb[c2 - 144];
                            g_Y[(size_t)c2 * NPIX + m] = v + bias;
                        }
                    } else {
                        Cout[((size_t)(b * OO + c2) << 12) + (m & 4095)] = v + ba[c2];
                    }
                }
            }
        }
    }
}

// -------- softmax + offsets -> packed bilinear weights/indices ------------
__global__ __launch_bounds__(256) void offmask_kernel() {
    int n = blockIdx.x * 256 + threadIdx.x;
    int g = blockIdx.y;
    int hw = n & 4095;
    int h = hw >> 6, w = hw & 63;

    float lg[KKT];
    float mx = -1e30f;
#pragma unroll
    for (int kk = 0; kk < KKT; kk++) {
        lg[kk] = g_Y[(size_t)(144 + g * KKT + kk) * NPIX + n];
        mx = fmaxf(mx, lg[kk]);
    }
    float s = 0.f;
#pragma unroll
    for (int kk = 0; kk < KKT; kk++) { lg[kk] = __expf(lg[kk] - mx); s += lg[kk]; }
    float inv = 1.f / s;

#pragma unroll
    for (int kk = 0; kk < KKT; kk++) {
        float a  = lg[kk] * inv;
        float dy = g_Y[(size_t)(g * 18 + 2 * kk    ) * NPIX + n];
        float dx = g_Y[(size_t)(g * 18 + 2 * kk + 1) * NPIX + n];
        float py = (float)(h - 1 + kk / 3) + dy;
        float px = (float)(w - 1 + kk % 3) + dx;

        float y0f = floorf(py), x0f = floorf(px);
        float fy = py - y0f, fx = px - x0f;
        y0f = fminf(fmaxf(y0f, -2.f), 65.f);
        x0f = fminf(fmaxf(x0f, -2.f), 65.f);
        int y0 = (int)y0f, x0 = (int)x0f;

        bool vy0 = (unsigned)y0       < (unsigned)HH;
        bool vy1 = (unsigned)(y0 + 1) < (unsigned)HH;
        bool vx0 = (unsigned)x0       < (unsigned)WW;
        bool vx1 = (unsigned)(x0 + 1) < (unsigned)WW;

        float w00 = (vy0 && vx0) ? (1.f - fy) * (1.f - fx) * a : 0.f;
        float w01 = (vy0 && vx1) ? (1.f - fy) * fx * a : 0.f;
        float w10 = (vy1 && vx0) ? fy * (1.f - fx) * a : 0.f;
        float w11 = (vy1 && vx1) ? fy * fx * a : 0.f;

        int r0  = min(max(y0,     0), HH - 1);
        int r1  = min(max(y0 + 1, 0), HH - 1);
        int cc0 = min(max(x0,     0), WW - 1);
        int cc1 = min(max(x0 + 1, 0), WW - 1);
        int pack = r0 | (r1 << 6) | (cc0 << 12) | (cc1 << 18);

        size_t o = (size_t)(g * KKT + kk) * NPIX + n;
        g_wq[o]  = make_float4(w00, w01, w10, w11);
        g_idx[o] = pack;
    }
}

// -------- sampler: wq/idx once per (pixel,g,tap), loop cg, write planes ---
__global__ __launch_bounds__(256) void sample_kernel(const float* __restrict__ x) {
    int n  = blockIdx.x * 256 + threadIdx.x;
    int gk = blockIdx.y;               // 0..71
    int g = gk / KKT, tap = gk - g * KKT;
    int b = n >> 12;

    size_t sidx = (size_t)gk * NPIX + n;
    float4 wq = g_wq[sidx];
    int pk = g_idx[sidx];
    int r0 = pk & 63, r1 = (pk >> 6) & 63;
    int c0 = (pk >> 12) & 63, c1 = (pk >> 18) & 63;
    int o00 = (r0 << 6) + c0, o01 = (r0 << 6) + c1;
    int o10 = (r1 << 6) + c0, o11 = (r1 << 6) + c1;

    const float* xb = x + ((size_t)(b * CC + g * CGR) << 12);
    const int kbase = g * 288 + tap;
#pragma unroll 4
    for (int cg = 0; cg < CGR; cg++) {
        const float* p = xb + ((size_t)cg << 12);
        float v = wq.x * p[o00] + wq.y * p[o01] + wq.z * p[o10] + wq.w * p[o11];
        uint16_t h, l;
        split_fp16(v, h, l);
        size_t a = (size_t)(kbase + cg * 9) * NPIX + n;
        g_Ah[a] = h;
        g_Al[a] = l;
    }
}

// --------------------------------------------------------------------------
extern "C" void kernel_launch(void* const* d_in, const int* in_sizes, int n_in,
                              void* d_out, int out_size) {
    const float* x      = nullptr;
    const float* w_off  = nullptr;
    const float* b_off  = nullptr;
    const float* w_attn = nullptr;
    const float* b_attn = nullptr;
    const float* w_out  = nullptr;
    const float* b_out  = nullptr;
    for (int i = 0; i < n_in; i++) {
        const float* p = (const float*)d_in[i];
        switch (in_sizes[i]) {
            case 8388608: x      = p; break;
            case 331776:  w_off  = p; break;
            case 144:     b_off  = p; break;
            case 165888:  w_attn = p; break;
            case 72:      b_attn = p; break;
            case 589824:  w_out  = p; break;
            case 256:     b_out  = p; break;
            default: break;
        }
    }
    if (!x || !w_off || !b_off || !w_attn || !b_attn || !w_out || !b_out)
        return;
    float* out = (float*)d_out;

    cudaFuncSetAttribute(mma_kernel<0>,
        cudaFuncAttributeMaxDynamicSharedMemorySize, SMEM_TOT);
    cudaFuncSetAttribute(mma_kernel<1>,
        cudaFuncAttributeMaxDynamicSharedMemorySize, SMEM_TOT);

    // 0) stage weights: fp32 -> fp16 hi plane word pairs
    stageB_kernel<<<(2 * 256 * KW) / 256, 256>>>(w_off, w_attn, w_out);

    // 1) offset/mask conv (HMMA 1-term, fused im2col) -> g_Y
    mma_kernel<0><<<NPIX / 128, 512, SMEM_TOT>>>(x, b_off, b_attn, nullptr);

    // 2) softmax + packed bilinear weights/indices
    offmask_kernel<<<dim3(NPIX / 256, GG), 256>>>();

    // 3) sampling pass: modulated bilinear gather -> fp16 hi/lo planes
    sample_kernel<<<dim3(NPIX / 256, GG * KKT), 256>>>(x);

    // 4) deformable conv (HMMA 2-term, A/B cp.async 8-stage) -> NCHW out
    mma_kernel<1><<<NPIX / 128, 512, SMEM_TOT>>>(x, b_out, nullptr, out);
}

// round 13
// speedup vs baseline: 2.2321x; 1.1253x over previous
#include <cuda_runtime.h>
#include <cuda_fp16.h>
#include <cstdint>
#include <cstddef>

#define BB 8
#define CC 256
#define HH 64
#define WW 64
#define GG 8
#define CGR 32
#define KKT 9
#define OO 256
#define NPIX (BB*HH*WW)        // 32768
#define KC (CC*KKT)            // 2304
#define KW (KC/2)              // 1152 b32 words per row
#define CO1 216
#define HWSZ (HH*WW)           // 4096
#define NCH (KC/16)            // 144 k16 steps

// smem rings: B 8 stages x 8KB; A 8 stages x 4KB (hi only)
#define B_STG_B 8192
#define A_BASE  65536
#define A_STG_B 4096
#define SMEM_TOT (A_BASE + 8*A_STG_B)   // 98304

// -------- scratch (static device globals) ---------------------------------
__device__ __align__(16) float    g_Y[(size_t)CO1 * NPIX];          // conv1 out
__device__ __align__(16) float4   g_wq[(size_t)(GG*KKT) * NPIX];    // bilinear wts * attn
__device__ __align__(16) int      g_idx[(size_t)(GG*KKT) * NPIX];   // packed indices
__device__ __align__(16) uint32_t g_Bw[2][256 * KW];                // weights fp16
__device__ __align__(16) uint16_t g_Ah[(size_t)KC * NPIX];          // sampled A fp16 plane

// -------- helpers ---------------------------------------------------------
__device__ __forceinline__ uint32_t smem_u32(const void* p) {
    uint32_t a;
    asm("{ .reg .u64 t; cvta.to.shared.u64 t, %1; cvt.u32.u64 %0, t; }"
        : "=r"(a) : "l"(p));
    return a;
}
__device__ __forceinline__ void cpasync16(uint32_t dst, const void* src) {
    asm volatile("cp.async.cg.shared.global [%0], [%1], 16;"
        :: "r"(dst), "l"(src) : "memory");
}
#define CP_COMMIT() asm volatile("cp.async.commit_group;" ::: "memory")
#define CP_WAIT6()  asm volatile("cp.async.wait_group 6;" ::: "memory")
#define CP_WAIT0()  asm volatile("cp.async.wait_group 0;" ::: "memory")
__device__ __forceinline__ void ldsm4(uint32_t* r, uint32_t addr) {
    asm volatile("ldmatrix.sync.aligned.m8n8.x4.shared.b16 {%0,%1,%2,%3}, [%4];"
        : "=r"(r[0]), "=r"(r[1]), "=r"(r[2]), "=r"(r[3]) : "r"(addr));
}
__device__ __forceinline__ void ldsm4t(uint32_t* r, uint32_t addr) {
    asm volatile("ldmatrix.sync.aligned.m8n8.x4.trans.shared.b16 {%0,%1,%2,%3}, [%4];"
        : "=r"(r[0]), "=r"(r[1]), "=r"(r[2]), "=r"(r[3]) : "r"(addr));
}
__device__ __forceinline__ void mma16816(float* c, const uint32_t* a,
                                         uint32_t b0, uint32_t b1) {
    asm volatile(
        "mma.sync.aligned.m16n8k16.row.col.f32.f16.f16.f32 "
        "{%0,%1,%2,%3}, {%4,%5,%6,%7}, {%8,%9}, {%0,%1,%2,%3};"
        : "+f"(c[0]), "+f"(c[1]), "+f"(c[2]), "+f"(c[3])
        : "r"(a[0]), "r"(a[1]), "r"(a[2]), "r"(a[3]), "r"(b0), "r"(b1));
}
__device__ __forceinline__ uint16_t to_fp16(float v) {
    __half hb = __float2half_rn(v);
    return *reinterpret_cast<uint16_t*>(&hb);
}

// -------- setup: weights -> fp16 word pairs -------------------------------
__global__ __launch_bounds__(256) void stageB_kernel(
    const float* __restrict__ w_off, const float* __restrict__ w_attn,
    const float* __restrict__ w_out)
{
    int idx = blockIdx.x * 256 + threadIdx.x;     // over 2*256*1152
    int gemm = idx / (256 * KW);
    int rem  = idx - gemm * (256 * KW);
    int row  = rem / KW;
    int wd   = rem - row * KW;
    int k    = wd * 2;
    float v0 = 0.f, v1 = 0.f;
    if (gemm == 0) {
        if (row < 144) {
            v0 = w_off[(size_t)row * KC + k];
            v1 = w_off[(size_t)row * KC + k + 1];
        } else if (row < CO1) {
            v0 = w_attn[(size_t)(row - 144) * KC + k];
            v1 = w_attn[(size_t)(row - 144) * KC + k + 1];
        }
    } else {
        v0 = w_out[(size_t)row * KC + k];
        v1 = w_out[(size_t)row * KC + k + 1];
    }
    g_Bw[gemm][row * KW + wd] =
        (uint32_t)to_fp16(v0) | ((uint32_t)to_fp16(v1) << 16);
}

// -------- main warp-MMA implicit GEMM (1-term fp16) -----------------------
// CTA: 128 pixels x 256 channels, K = 2304. 512 threads / 16 warps (4m x 4n).
// EPI==0: A = im2col(x) computed in-kernel; B cp.async 8-stage -> g_Y
// EPI==1: A & B pure cp.async copies, 8-stage rings -> NCHW out
template <int EPI>
__global__ __launch_bounds__(512, 1) void mma_kernel(
    const float* __restrict__ x,
    const float* __restrict__ ba,
    const float* __restrict__ bb,
    float* __restrict__ Cout)
{
    extern __shared__ __align__(16) char smem[];
    const uint32_t sb = smem_u32(smem);
    const int tid  = threadIdx.x;
    const int lane = tid & 31;
    const int wid  = tid >> 5;
    const int wm   = wid & 3;      // warp m-index (x32)
    const int wn   = wid >> 2;     // warp n-index (x64)
    const int m0   = blockIdx.x * 128;
    const int b    = m0 >> 12;

    // EPI0 producer mapping: (m, word w) for m and m+64
    const int pm = tid >> 3;       // 0..63
    const int pw = tid & 7;        // word 0..7 (k = c*16 + pw*2)

    // EPI1 A-copy mapping (threads 0..255): (k-row, 16B seg)
    const int cs  = tid & 15;            // seg
    const int ckl = (tid >> 4) & 15;     // k-row

    // ---- ldmatrix per-lane offsets (relative to stage bases) ----
    int offAh[2], offBh[4];
    if (EPI == 0) {
        const int rA   = lane & 15;
        const int segA = lane >> 4;
#pragma unroll
        for (int mt = 0; mt < 2; mt++) {
            int row = wm * 32 + mt * 16 + rA;
            offAh[mt] = row * 32 + (((segA * 4) ^ (rA & 4)) << 2);
        }
    } else {
        const int kr = (lane & 7) + ((lane & 16) ? 8 : 0);
        const int mo = (lane & 8) ? 1 : 0;
#pragma unroll
        for (int mt = 0; mt < 2; mt++) {
            int mseg = wm * 4 + mt * 2 + mo;
            offAh[mt] = kr * 256 + ((mseg ^ (kr & 7)) << 4);
        }
    }
    {
        const int rB   = (lane & 7) + ((lane & 16) ? 8 : 0);
        const int segB = (lane >> 3) & 1;
#pragma unroll
        for (int ntp = 0; ntp < 4; ntp++) {
            int row = wn * 64 + ntp * 16 + rB;
            offBh[ntp] = row * 32 + (((segB * 4) ^ (rB & 4)) << 2);
        }
    }

    // B-copy mapping: 512 threads x 16B = full 8KB plane
    const int bn = tid >> 1;
    const int bq = tid & 1;
    const int bdw = (bn * 8 + ((bq * 4) ^ (bn & 4))) * 4;  // byte offset in plane

    float cr[2][8][4];
#pragma unroll
    for (int mt = 0; mt < 2; mt++)
#pragma unroll
        for (int nt = 0; nt < 8; nt++)
#pragma unroll
            for (int j = 0; j < 4; j++) cr[mt][nt][j] = 0.f;

    const uint32_t* __restrict__ Bh = g_Bw[EPI];

    // ---- async producers ----
    auto cpB = [&](int c) {
        if (c < NCH) {
            uint32_t dst = sb + (c & 7) * B_STG_B + bdw;
            cpasync16(dst, &Bh[bn * KW + c * 8 + bq * 4]);
            if (EPI == 1 && tid < 256) {
                uint32_t adst = sb + A_BASE + (c & 7) * A_STG_B
                              + ckl * 256 + ((cs ^ (ckl & 7)) << 4);
                const uint16_t* src = g_Ah
                    + (size_t)(c * 16 + ckl) * NPIX + m0 + cs * 8;
                cpasync16(adst, src);
            }
        }
        CP_COMMIT();
    };

    // EPI0 split producer: LDG phase (issued before MMAs), STS phase (after)
    auto ldgA = [&](int c, float pv[2][2]) {
        if (EPI != 0 || c >= NCH) return;
#pragma unroll
        for (int half = 0; half < 2; half++) {
            const int mg = m0 + pm + half * 64;
            const int hh = (mg & 4095) >> 6;
            const int ww = mg & 63;
            const int k  = c * 16 + pw * 2;
#pragma unroll
            for (int u = 0; u < 2; u++) {
                int kk  = k + u;
                int ci  = kk / 9;
                int tap = kk - ci * 9;
                int dy = tap / 3 - 1, dx = tap - (tap / 3) * 3 - 1;
                int y = hh + dy, xx2 = ww + dx;
                pv[half][u] = ((unsigned)y < (unsigned)HH &&
                               (unsigned)xx2 < (unsigned)WW)
                    ? x[((size_t)(b * CC + ci) << 12) + (y << 6) + xx2] : 0.f;
            }
        }
    };
    auto stsA = [&](int c, float pv[2][2]) {
        if (EPI != 0 || c >= NCH) return;
        char* stp = smem + A_BASE + (c & 1) * A_STG_B;
#pragma unroll
        for (int half = 0; half < 2; half++) {
            const int m = pm + half * 64;
            int dw = m * 8 + (pw ^ (m & 4));
            *(uint32_t*)(stp + dw * 4) =
                (uint32_t)to_fp16(pv[half][0]) |
                ((uint32_t)to_fp16(pv[half][1]) << 16);
        }
    };

    // ---- prologue: 7 async groups in flight; EPI0 computes+stores A(0) ----
    cpB(0); cpB(1); cpB(2); cpB(3); cpB(4); cpB(5); cpB(6);
    float pv[2][2];
    if (EPI == 0) { ldgA(0, pv); stsA(0, pv); }

    for (int c = 0; c < NCH; c++) {
        CP_WAIT6();               // stage c resident (<=6 groups pending)
        __syncthreads();          // + all warps done reading recycled stages

        ldgA(c + 1, pv);          // EPI0: issue gathers early (covered by MMAs)
        cpB(c + 7);

        // ---- consume stage c ----
        const uint32_t stbB = sb + (c & 7) * B_STG_B;
        const uint32_t stbA = sb + A_BASE
                            + ((EPI == 0) ? (c & 1) : (c & 7)) * A_STG_B;
        uint32_t ah[2][4];
#pragma unroll
        for (int mt = 0; mt < 2; mt++) {
            if (EPI == 0) ldsm4(ah[mt], stbA + offAh[mt]);
            else          ldsm4t(ah[mt], stbA + offAh[mt]);
        }
#pragma unroll
        for (int ntp = 0; ntp < 4; ntp++) {
            // GEMM0: channels >= 216 are zero padding -> skip (warp-uniform)
            if (EPI == 0 && wn * 64 + ntp * 16 >= CO1) continue;
            uint32_t bh[4];
            ldsm4(bh, stbB + offBh[ntp]);
#pragma unroll
            for (int j = 0; j < 2; j++) {
                const int nt = ntp * 2 + j;
                if (EPI == 0 && wn * 64 + ntp * 16 + j * 8 >= CO1) continue;
#pragma unroll
                for (int mt = 0; mt < 2; mt++)
                    mma16816(cr[mt][nt], ah[mt], bh[2 * j], bh[2 * j + 1]);
            }
        }

        stsA(c + 1, pv);          // EPI0: store after MMAs (latency hidden)
    }
    CP_WAIT0();

    // ---- epilogue ----
    const int eg = lane >> 2;
    const int et = lane & 3;
#pragma unroll
    for (int mt = 0; mt < 2; mt++) {
#pragma unroll
        for (int nt = 0; nt < 8; nt++) {
            const float* cc = cr[mt][nt];
            int mloc = wm * 32 + mt * 16 + eg;
            int co   = wn * 64 + nt * 8 + et * 2;
#pragma unroll
            for (int rr = 0; rr < 2; rr++) {
                int m = m0 + mloc + rr * 8;
#pragma unroll
                for (int cw = 0; cw < 2; cw++) {
                    int c2 = co + cw;
                    float v = cc[rr * 2 + cw];
                    if (EPI == 0) {
                        if (c2 < CO1) {
                            float bias = (c2 < 144) ? ba[c2] : bb[c2 - 144];
                            g_Y[(size_t)c2 * NPIX + m] = v + bias;
                        }
                    } else {
                        Cout[((size_t)(b * OO + c2) << 12) + (m & 4095)] = v + ba[c2];
                    }
                }
            }
        }
    }
}

// -------- softmax + offsets -> packed bilinear weights/indices ------------
__global__ __launch_bounds__(256) void offmask_kernel() {
    int n = blockIdx.x * 256 + threadIdx.x;
    int g = blockIdx.y;
    int hw = n & 4095;
    int h = hw >> 6, w = hw & 63;

    float lg[KKT];
    float mx = -1e30f;
#pragma unroll
    for (int kk = 0; kk < KKT; kk++) {
        lg[kk] = g_Y[(size_t)(144 + g * KKT + kk) * NPIX + n];
        mx = fmaxf(mx, lg[kk]);
    }
    float s = 0.f;
#pragma unroll
    for (int kk = 0; kk < KKT; kk++) { lg[kk] = __expf(lg[kk] - mx); s += lg[kk]; }
    float inv = 1.f / s;

#pragma unroll
    for (int kk = 0; kk < KKT; kk++) {
        float a  = lg[kk] * inv;
        float dy = g_Y[(size_t)(g * 18 + 2 * kk    ) * NPIX + n];
        float dx = g_Y[(size_t)(g * 18 + 2 * kk + 1) * NPIX + n];
        float py = (float)(h - 1 + kk / 3) + dy;
        float px = (float)(w - 1 + kk % 3) + dx;

        float y0f = floorf(py), x0f = floorf(px);
        float fy = py - y0f, fx = px - x0f;
        y0f = fminf(fmaxf(y0f, -2.f), 65.f);
        x0f = fminf(fmaxf(x0f, -2.f), 65.f);
        int y0 = (int)y0f, x0 = (int)x0f;

        bool vy0 = (unsigned)y0       < (unsigned)HH;
        bool vy1 = (unsigned)(y0 + 1) < (unsigned)HH;
        bool vx0 = (unsigned)x0       < (unsigned)WW;
        bool vx1 = (unsigned)(x0 + 1) < (unsigned)WW;

        float w00 = (vy0 && vx0) ? (1.f - fy) * (1.f - fx) * a : 0.f;
        float w01 = (vy0 && vx1) ? (1.f - fy) * fx * a : 0.f;
        float w10 = (vy1 && vx0) ? fy * (1.f - fx) * a : 0.f;
        float w11 = (vy1 && vx1) ? fy * fx * a : 0.f;

        int r0  = min(max(y0,     0), HH - 1);
        int r1  = min(max(y0 + 1, 0), HH - 1);
        int cc0 = min(max(x0,     0), WW - 1);
        int cc1 = min(max(x0 + 1, 0), WW - 1);
        int pack = r0 | (r1 << 6) | (cc0 << 12) | (cc1 << 18);

        size_t o = (size_t)(g * KKT + kk) * NPIX + n;
        g_wq[o]  = make_float4(w00, w01, w10, w11);
        g_idx[o] = pack;
    }
}

// -------- sampler: wq/idx once per (pixel,g,tap), loop cg, write plane ----
__global__ __launch_bounds__(256) void sample_kernel(const float* __restrict__ x) {
    int n  = blockIdx.x * 256 + threadIdx.x;
    int gk = blockIdx.y;               // 0..71
    int g = gk / KKT, tap = gk - g * KKT;
    int b = n >> 12;

    size_t sidx = (size_t)gk * NPIX + n;
    float4 wq = g_wq[sidx];
    int pk = g_idx[sidx];
    int r0 = pk & 63, r1 = (pk >> 6) & 63;
    int c0 = (pk >> 12) & 63, c1 = (pk >> 18) & 63;
    int o00 = (r0 << 6) + c0, o01 = (r0 << 6) + c1;
    int o10 = (r1 << 6) + c0, o11 = (r1 << 6) + c1;

    const float* xb = x + ((size_t)(b * CC + g * CGR) << 12);
    const int kbase = g * 288 + tap;
#pragma unroll 4
    for (int cg = 0; cg < CGR; cg++) {
        const float* p = xb + ((size_t)cg << 12);
        float v = wq.x * p[o00] + wq.y * p[o01] + wq.z * p[o10] + wq.w * p[o11];
        g_Ah[(size_t)(kbase + cg * 9) * NPIX + n] = to_fp16(v);
    }
}

// --------------------------------------------------------------------------
extern "C" void kernel_launch(void* const* d_in, const int* in_sizes, int n_in,
                              void* d_out, int out_size) {
    const float* x      = nullptr;
    const float* w_off  = nullptr;
    const float* b_off  = nullptr;
    const float* w_attn = nullptr;
    const float* b_attn = nullptr;
    const float* w_out  = nullptr;
    const float* b_out  = nullptr;
    for (int i = 0; i < n_in; i++) {
        const float* p = (const float*)d_in[i];
        switch (in_sizes[i]) {
            case 8388608: x      = p; break;
            case 331776:  w_off  = p; break;
            case 144:     b_off  = p; break;
            case 165888:  w_attn = p; break;
            case 72:      b_attn = p; break;
            case 589824:  w_out  = p; break;
            case 256:     b_out  = p; break;
            default: break;
        }
    }
    if (!x || !w_off || !b_off || !w_attn || !b_attn || !w_out || !b_out)
        return;
    float* out = (float*)d_out;

    cudaFuncSetAttribute(mma_kernel<0>,
        cudaFuncAttributeMaxDynamicSharedMemorySize, SMEM_TOT);
    cudaFuncSetAttribute(mma_kernel<1>,
        cudaFuncAttributeMaxDynamicSharedMemorySize, SMEM_TOT);

    // 0) stage weights: fp32 -> fp16 word pairs
    stageB_kernel<<<(2 * 256 * KW) / 256, 256>>>(w_off, w_attn, w_out);

    // 1) offset/mask conv (HMMA 1-term, fused im2col) -> g_Y
    mma_kernel<0><<<NPIX / 128, 512, SMEM_TOT>>>(x, b_off, b_attn, nullptr);

    // 2) softmax + packed bilinear weights/indices
    offmask_kernel<<<dim3(NPIX / 256, GG), 256>>>();

    // 3) sampling pass: modulated bilinear gather -> fp16 plane
    sample_kernel<<<dim3(NPIX / 256, GG * KKT), 256>>>(x);

    // 4) deformable conv (HMMA 1-term, A/B cp.async 8-stage) -> NCHW out
    mma_kernel<1><<<NPIX / 128, 512, SMEM_TOT>>>(x, b_out, nullptr, out);
}

// round 14
// speedup vs baseline: 2.5207x; 1.1293x over previous
#include <cuda_runtime.h>
#include <cuda_fp16.h>
#include <cstdint>
#include <cstddef>

#define BB 8
#define CC 256
#define HH 64
#define WW 64
#define GG 8
#define CGR 32
#define KKT 9
#define OO 256
#define NPIX (BB*HH*WW)        // 32768
#define KC (CC*KKT)            // 2304
#define KW (KC/2)              // 1152 b32 words per row
#define CO1 216
#define HWSZ (HH*WW)           // 4096
#define NCH (KC/16)            // 144 k16 steps

// smem rings: B 8 stages x 8KB; A 8 stages x 4KB
#define B_STG_B 8192
#define A_BASE  65536
#define A_STG_B 4096
#define SMEM_TOT (A_BASE + 8*A_STG_B)   // 98304

// -------- scratch (static device globals) ---------------------------------
__device__ __align__(16) float    g_Y[(size_t)CO1 * NPIX];          // conv1 out
__device__ __align__(16) float4   g_wq[(size_t)(GG*KKT) * NPIX];    // bilinear wts * attn
__device__ __align__(16) int      g_idx[(size_t)(GG*KKT) * NPIX];   // packed indices
__device__ __align__(16) uint32_t g_Bw[2][256 * KW];                // weights fp16
__device__ __align__(16) uint16_t g_Ah[(size_t)KC * NPIX];          // sampled A fp16 plane

// -------- helpers ---------------------------------------------------------
__device__ __forceinline__ uint32_t smem_u32(const void* p) {
    uint32_t a;
    asm("{ .reg .u64 t; cvta.to.shared.u64 t, %1; cvt.u32.u64 %0, t; }"
        : "=r"(a) : "l"(p));
    return a;
}
__device__ __forceinline__ void cpasync16(uint32_t dst, const void* src) {
    asm volatile("cp.async.cg.shared.global [%0], [%1], 16;"
        :: "r"(dst), "l"(src) : "memory");
}
#define CP_COMMIT() asm volatile("cp.async.commit_group;" ::: "memory")
#define CP_WAIT2()  asm volatile("cp.async.wait_group 2;" ::: "memory")
#define CP_WAIT0()  asm volatile("cp.async.wait_group 0;" ::: "memory")
__device__ __forceinline__ void ldsm4(uint32_t* r, uint32_t addr) {
    asm volatile("ldmatrix.sync.aligned.m8n8.x4.shared.b16 {%0,%1,%2,%3}, [%4];"
        : "=r"(r[0]), "=r"(r[1]), "=r"(r[2]), "=r"(r[3]) : "r"(addr));
}
__device__ __forceinline__ void ldsm4t(uint32_t* r, uint32_t addr) {
    asm volatile("ldmatrix.sync.aligned.m8n8.x4.trans.shared.b16 {%0,%1,%2,%3}, [%4];"
        : "=r"(r[0]), "=r"(r[1]), "=r"(r[2]), "=r"(r[3]) : "r"(addr));
}
__device__ __forceinline__ void mma16816(float* c, const uint32_t* a,
                                         uint32_t b0, uint32_t b1) {
    asm volatile(
        "mma.sync.aligned.m16n8k16.row.col.f32.f16.f16.f32 "
        "{%0,%1,%2,%3}, {%4,%5,%6,%7}, {%8,%9}, {%0,%1,%2,%3};"
        : "+f"(c[0]), "+f"(c[1]), "+f"(c[2]), "+f"(c[3])
        : "r"(a[0]), "r"(a[1]), "r"(a[2]), "r"(a[3]), "r"(b0), "r"(b1));
}
__device__ __forceinline__ uint16_t to_fp16(float v) {
    __half hb = __float2half_rn(v);
    return *reinterpret_cast<uint16_t*>(&hb);
}

// -------- setup: weights -> fp16 word pairs -------------------------------
__global__ __launch_bounds__(256) void stageB_kernel(
    const float* __restrict__ w_off, const float* __restrict__ w_attn,
    const float* __restrict__ w_out)
{
    int idx = blockIdx.x * 256 + threadIdx.x;     // over 2*256*1152
    int gemm = idx / (256 * KW);
    int rem  = idx - gemm * (256 * KW);
    int row  = rem / KW;
    int wd   = rem - row * KW;
    int k    = wd * 2;
    float v0 = 0.f, v1 = 0.f;
    if (gemm == 0) {
        if (row < 144) {
            v0 = w_off[(size_t)row * KC + k];
            v1 = w_off[(size_t)row * KC + k + 1];
        } else if (row < CO1) {
            v0 = w_attn[(size_t)(row - 144) * KC + k];
            v1 = w_attn[(size_t)(row - 144) * KC + k + 1];
        }
    } else {
        v0 = w_out[(size_t)row * KC + k];
        v1 = w_out[(size_t)row * KC + k + 1];
    }
    g_Bw[gemm][row * KW + wd] =
        (uint32_t)to_fp16(v0) | ((uint32_t)to_fp16(v1) << 16);
}

// -------- main warp-MMA implicit GEMM (1-term fp16, K=32/iter) ------------
// CTA: 128 pixels x 256 channels, K = 2304. 512 threads / 16 warps (4m x 4n).
// EPI==0: A = im2col(x) computed in-kernel; B cp.async -> g_Y
// EPI==1: A & B pure cp.async copies -> NCHW out
template <int EPI>
__global__ __launch_bounds__(512, 1) void mma_kernel(
    const float* __restrict__ x,
    const float* __restrict__ ba,
    const float* __restrict__ bb,
    float* __restrict__ Cout)
{
    extern __shared__ __align__(16) char smem[];
    const uint32_t sb = smem_u32(smem);
    const int tid  = threadIdx.x;
    const int lane = tid & 31;
    const int wid  = tid >> 5;
    const int wm   = wid & 3;      // warp m-index (x32)
    const int wn   = wid >> 2;     // warp n-index (x64)
    const int m0   = blockIdx.x * 128;
    const int b    = m0 >> 12;

    // EPI0 producer mapping: (m, word w) for m and m+64
    const int pm = tid >> 3;       // 0..63
    const int pw = tid & 7;        // word 0..7 (k = c*16 + pw*2)

    // EPI1 A-copy mapping (threads 0..255): (k-row, 16B seg)
    const int cs  = tid & 15;            // seg
    const int ckl = (tid >> 4) & 15;     // k-row

    // ---- ldmatrix per-lane offsets (relative to stage bases) ----
    int offAh[2], offBh[4];
    if (EPI == 0) {
        const int rA   = lane & 15;
        const int segA = lane >> 4;
#pragma unroll
        for (int mt = 0; mt < 2; mt++) {
            int row = wm * 32 + mt * 16 + rA;
            offAh[mt] = row * 32 + (((segA * 4) ^ (rA & 4)) << 2);
        }
    } else {
        const int kr = (lane & 7) + ((lane & 16) ? 8 : 0);
        const int mo = (lane & 8) ? 1 : 0;
#pragma unroll
        for (int mt = 0; mt < 2; mt++) {
            int mseg = wm * 4 + mt * 2 + mo;
            offAh[mt] = kr * 256 + ((mseg ^ (kr & 7)) << 4);
        }
    }
    {
        const int rB   = (lane & 7) + ((lane & 16) ? 8 : 0);
        const int segB = (lane >> 3) & 1;
#pragma unroll
        for (int ntp = 0; ntp < 4; ntp++) {
            int row = wn * 64 + ntp * 16 + rB;
            offBh[ntp] = row * 32 + (((segB * 4) ^ (rB & 4)) << 2);
        }
    }

    // B-copy mapping: 512 threads x 16B = full 8KB plane
    const int bn = tid >> 1;
    const int bq = tid & 1;
    const int bdw = (bn * 8 + ((bq * 4) ^ (bn & 4))) * 4;  // byte offset in plane

    float cr[2][8][4];
#pragma unroll
    for (int mt = 0; mt < 2; mt++)
#pragma unroll
        for (int nt = 0; nt < 8; nt++)
#pragma unroll
            for (int j = 0; j < 4; j++) cr[mt][nt][j] = 0.f;

    const uint32_t* __restrict__ Bh = g_Bw[EPI];

    // ---- async producer: one chunk's copies (no commit) ----
    auto cpChunk = [&](int c) {
        if (c >= NCH) return;
        uint32_t dst = sb + (c & 7) * B_STG_B + bdw;
        cpasync16(dst, &Bh[bn * KW + c * 8 + bq * 4]);
        if (EPI == 1 && tid < 256) {
            uint32_t adst = sb + A_BASE + (c & 7) * A_STG_B
                          + ckl * 256 + ((cs ^ (ckl & 7)) << 4);
            const uint16_t* src = g_Ah
                + (size_t)(c * 16 + ckl) * NPIX + m0 + cs * 8;
            cpasync16(adst, src);
        }
    };
    auto cpB2 = [&](int c) {     // two chunks -> ONE commit group
        cpChunk(c);
        cpChunk(c + 1);
        CP_COMMIT();
    };

    // EPI0 split producer: LDG phase (issued before MMAs), STS phase (after)
    auto ldgA = [&](int c, float pv[2][2]) {
        if (EPI != 0 || c >= NCH) return;
#pragma unroll
        for (int half = 0; half < 2; half++) {
            const int mg = m0 + pm + half * 64;
            const int hh = (mg & 4095) >> 6;
            const int ww = mg & 63;
            const int k  = c * 16 + pw * 2;
#pragma unroll
            for (int u = 0; u < 2; u++) {
                int kk  = k + u;
                int ci  = kk / 9;
                int tap = kk - ci * 9;
                int dy = tap / 3 - 1, dx = tap - (tap / 3) * 3 - 1;
                int y = hh + dy, xx2 = ww + dx;
                pv[half][u] = ((unsigned)y < (unsigned)HH &&
                               (unsigned)xx2 < (unsigned)WW)
                    ? x[((size_t)(b * CC + ci) << 12) + (y << 6) + xx2] : 0.f;
            }
        }
    };
    auto stsA = [&](int c, float pv[2][2]) {
        if (EPI != 0 || c >= NCH) return;
        char* stp = smem + A_BASE + (c & 7) * A_STG_B;
#pragma unroll
        for (int half = 0; half < 2; half++) {
            const int m = pm + half * 64;
            int dw = m * 8 + (pw ^ (m & 4));
            *(uint32_t*)(stp + dw * 4) =
                (uint32_t)to_fp16(pv[half][0]) |
                ((uint32_t)to_fp16(pv[half][1]) << 16);
        }
    };

    // ---- consume one chunk ----
    auto consume = [&](int cc) {
        const uint32_t stbB = sb + (cc & 7) * B_STG_B;
        const uint32_t stbA = sb + A_BASE + (cc & 7) * A_STG_B;
        uint32_t ah[2][4];
#pragma unroll
        for (int mt = 0; mt < 2; mt++) {
            if (EPI == 0) ldsm4(ah[mt], stbA + offAh[mt]);
            else          ldsm4t(ah[mt], stbA + offAh[mt]);
        }
#pragma unroll
        for (int ntp = 0; ntp < 4; ntp++) {
            // GEMM0: channels >= 216 are zero padding -> skip (warp-uniform)
            if (EPI == 0 && wn * 64 + ntp * 16 >= CO1) continue;
            uint32_t bh[4];
            ldsm4(bh, stbB + offBh[ntp]);
#pragma unroll
            for (int j = 0; j < 2; j++) {
                const int nt = ntp * 2 + j;
                if (EPI == 0 && wn * 64 + ntp * 16 + j * 8 >= CO1) continue;
#pragma unroll
                for (int mt = 0; mt < 2; mt++)
                    mma16816(cr[mt][nt], ah[mt], bh[2 * j], bh[2 * j + 1]);
            }
        }
    };

    // ---- prologue: 3 groups (chunks 0-5) in flight; EPI0 stores A(0,1) ----
    cpB2(0); cpB2(2); cpB2(4);
    float pvA[2][2], pvB[2][2];
    if (EPI == 0) {
        ldgA(0, pvA); stsA(0, pvA);
        ldgA(1, pvB); stsA(1, pvB);
    }

    for (int c = 0; c < NCH; c += 2) {
        CP_WAIT2();               // chunks c, c+1 resident (<=2 groups pending)
        __syncthreads();          // + all warps done reading recycled stages

        ldgA(c + 2, pvA);         // EPI0: issue both chunks' gathers early
        ldgA(c + 3, pvB);
        cpB2(c + 6);

        consume(c);
        consume(c + 1);

        stsA(c + 2, pvA);         // EPI0: store after MMAs (latency hidden)
        stsA(c + 3, pvB);
    }
    CP_WAIT0();

    // ---- epilogue ----
    const int eg = lane >> 2;
    const int et = lane & 3;
#pragma unroll
    for (int mt = 0; mt < 2; mt++) {
#pragma unroll
        for (int nt = 0; nt < 8; nt++) {
            const float* cc = cr[mt][nt];
            int mloc = wm * 32 + mt * 16 + eg;
            int co   = wn * 64 + nt * 8 + et * 2;
#pragma unroll
            for (int rr = 0; rr < 2; rr++) {
                int m = m0 + mloc + rr * 8;
#pragma unroll
                for (int cw = 0; cw < 2; cw++) {
                    int c2 = co + cw;
                    float v = cc[rr * 2 + cw];
                    if (EPI == 0) {
                        if (c2 < CO1) {
                            float bias = (c2 < 144) ? ba[c2] : bb[c2 - 144];
                            g_Y[(size_t)c2 * NPIX + m] = v + bias;
                        }
                    } else {
                        Cout[((size_t)(b * OO + c2) << 12) + (m & 4095)] = v + ba[c2];
                    }
                }
            }
        }
    }
}

// -------- softmax + offsets -> packed bilinear weights/indices ------------
__global__ __launch_bounds__(256) void offmask_kernel() {
    int n = blockIdx.x * 256 + threadIdx.x;
    int g = blockIdx.y;
    int hw = n & 4095;
    int h = hw >> 6, w = hw & 63;

    float lg[KKT];
    float mx = -1e30f;
#pragma unroll
    for (int kk = 0; kk < KKT; kk++) {
        lg[kk] = g_Y[(size_t)(144 + g * KKT + kk) * NPIX + n];
        mx = fmaxf(mx, lg[kk]);
    }
    float s = 0.f;
#pragma unroll
    for (int kk = 0; kk < KKT; kk++) { lg[kk] = __expf(lg[kk] - mx); s += lg[kk]; }
    float inv = 1.f / s;

#pragma unroll
    for (int kk = 0; kk < KKT; kk++) {
        float a  = lg[kk] * inv;
        float dy = g_Y[(size_t)(g * 18 + 2 * kk    ) * NPIX + n];
        float dx = g_Y[(size_t)(g * 18 + 2 * kk + 1) * NPIX + n];
        float py = (float)(h - 1 + kk / 3) + dy;
        float px = (float)(w - 1 + kk % 3) + dx;

        float y0f = floorf(py), x0f = floorf(px);
        float fy = py - y0f, fx = px - x0f;
        y0f = fminf(fmaxf(y0f, -2.f), 65.f);
        x0f = fminf(fmaxf(x0f, -2.f), 65.f);
        int y0 = (int)y0f, x0 = (int)x0f;

        bool vy0 = (unsigned)y0       < (unsigned)HH;
        bool vy1 = (unsigned)(y0 + 1) < (unsigned)HH;
        bool vx0 = (unsigned)x0       < (unsigned)WW;
        bool vx1 = (unsigned)(x0 + 1) < (unsigned)WW;

        float w00 = (vy0 && vx0) ? (1.f - fy) * (1.f - fx) * a : 0.f;
        float w01 = (vy0 && vx1) ? (1.f - fy) * fx * a : 0.f;
        float w10 = (vy1 && vx0) ? fy * (1.f - fx) * a : 0.f;
        float w11 = (vy1 && vx1) ? fy * fx * a : 0.f;

        int r0  = min(max(y0,     0), HH - 1);
        int r1  = min(max(y0 + 1, 0), HH - 1);
        int cc0 = min(max(x0,     0), WW - 1);
        int cc1 = min(max(x0 + 1, 0), WW - 1);
        int pack = r0 | (r1 << 6) | (cc0 << 12) | (cc1 << 18);

        size_t o = (size_t)(g * KKT + kk) * NPIX + n;
        g_wq[o]  = make_float4(w00, w01, w10, w11);
        g_idx[o] = pack;
    }
}

// -------- sampler: wq/idx once per (pixel,g,tap), loop cg, write plane ----
__global__ __launch_bounds__(256) void sample_kernel(const float* __restrict__ x) {
    int n  = blockIdx.x * 256 + threadIdx.x;
    int gk = blockIdx.y;               // 0..71
    int g = gk / KKT, tap = gk - g * KKT;
    int b = n >> 12;

    size_t sidx = (size_t)gk * NPIX + n;
    float4 wq = g_wq[sidx];
    int pk = g_idx[sidx];
    int r0 = pk & 63, r1 = (pk >> 6) & 63;
    int c0 = (pk >> 12) & 63, c1 = (pk >> 18) & 63;
    int o00 = (r0 << 6) + c0, o01 = (r0 << 6) + c1;
    int o10 = (r1 << 6) + c0, o11 = (r1 << 6) + c1;

    const float* xb = x + ((size_t)(b * CC + g * CGR) << 12);
    const int kbase = g * 288 + tap;
#pragma unroll 4
    for (int cg = 0; cg < CGR; cg++) {
        const float* p = xb + ((size_t)cg << 12);
        float v = wq.x * p[o00] + wq.y * p[o01] + wq.z * p[o10] + wq.w * p[o11];
        g_Ah[(size_t)(kbase + cg * 9) * NPIX + n] = to_fp16(v);
    }
}

// --------------------------------------------------------------------------
extern "C" void kernel_launch(void* const* d_in, const int* in_sizes, int n_in,
                              void* d_out, int out_size) {
    const float* x      = nullptr;
    const float* w_off  = nullptr;
    const float* b_off  = nullptr;
    const float* w_attn = nullptr;
    const float* b_attn = nullptr;
    const float* w_out  = nullptr;
    const float* b_out  = nullptr;
    for (int i = 0; i < n_in; i++) {
        const float* p = (const float*)d_in[i];
        switch (in_sizes[i]) {
            case 8388608: x      = p; break;
            case 331776:  w_off  = p; break;
            case 144:     b_off  = p; break;
            case 165888:  w_attn = p; break;
            case 72:      b_attn = p; break;
            case 589824:  w_out  = p; break;
            case 256:     b_out  = p; break;
            default: break;
        }
    }
    if (!x || !w_off || !b_off || !w_attn || !b_attn || !w_out || !b_out)
        return;
    float* out = (float*)d_out;

    cudaFuncSetAttribute(mma_kernel<0>,
        cudaFuncAttributeMaxDynamicSharedMemorySize, SMEM_TOT);
    cudaFuncSetAttribute(mma_kernel<1>,
        cudaFuncAttributeMaxDynamicSharedMemorySize, SMEM_TOT);

    // 0) stage weights: fp32 -> fp16 word pairs
    stageB_kernel<<<(2 * 256 * KW) / 256, 256>>>(w_off, w_attn, w_out);

    // 1) offset/mask conv (HMMA 1-term, fused im2col, K=32/iter) -> g_Y
    mma_kernel<0><<<NPIX / 128, 512, SMEM_TOT>>>(x, b_off, b_attn, nullptr);

    // 2) softmax + packed bilinear weights/indices
    offmask_kernel<<<dim3(NPIX / 256, GG), 256>>>();

    // 3) sampling pass: modulated bilinear gather -> fp16 plane
    sample_kernel<<<dim3(NPIX / 256, GG * KKT), 256>>>(x);

    // 4) deformable conv (HMMA 1-term, A/B cp.async, K=32/iter) -> NCHW out
    mma_kernel<1><<<NPIX / 128, 512, SMEM_TOT>>>(x, b_out, nullptr, out);
}

// round 15
// speedup vs baseline: 2.6127x; 1.0365x over previous
#include <cuda_runtime.h>
#include <cuda_fp16.h>
#include <cstdint>
#include <cstddef>

#define BB 8
#define CC 256
#define HH 64
#define WW 64
#define GG 8
#define CGR 32
#define KKT 9
#define OO 256
#define NPIX (BB*HH*WW)        // 32768
#define KC (CC*KKT)            // 2304
#define KW (KC/2)              // 1152 b32 words per row
#define CO1 216
#define HWSZ (HH*WW)           // 4096
#define NCH (KC/16)            // 144 k16 steps

// smem rings: B 16 stages x 8KB; A 16 stages x 4KB
#define B_STG_B 8192
#define A_BASE  131072
#define A_STG_B 4096
#define SMEM_TOT (A_BASE + 16*A_STG_B)   // 196608

// -------- scratch (static device globals) ---------------------------------
__device__ __align__(16) float    g_Y[(size_t)CO1 * NPIX];          // conv1 out
__device__ __align__(16) float4   g_wq[(size_t)(GG*KKT) * NPIX];    // bilinear wts * attn
__device__ __align__(16) int      g_idx[(size_t)(GG*KKT) * NPIX];   // packed indices
__device__ __align__(16) uint32_t g_Bw[2][256 * KW];                // weights fp16
__device__ __align__(16) uint16_t g_Ah[(size_t)KC * NPIX];          // sampled A fp16 plane

// -------- helpers ---------------------------------------------------------
__device__ __forceinline__ uint32_t smem_u32(const void* p) {
    uint32_t a;
    asm("{ .reg .u64 t; cvta.to.shared.u64 t, %1; cvt.u32.u64 %0, t; }"
        : "=r"(a) : "l"(p));
    return a;
}
__device__ __forceinline__ void cpasync16(uint32_t dst, const void* src) {
    asm volatile("cp.async.cg.shared.global [%0], [%1], 16;"
        :: "r"(dst), "l"(src) : "memory");
}
#define CP_COMMIT() asm volatile("cp.async.commit_group;" ::: "memory")
#define CP_WAIT2()  asm volatile("cp.async.wait_group 2;" ::: "memory")
#define CP_WAIT0()  asm volatile("cp.async.wait_group 0;" ::: "memory")
__device__ __forceinline__ void ldsm4(uint32_t* r, uint32_t addr) {
    asm volatile("ldmatrix.sync.aligned.m8n8.x4.shared.b16 {%0,%1,%2,%3}, [%4];"
        : "=r"(r[0]), "=r"(r[1]), "=r"(r[2]), "=r"(r[3]) : "r"(addr));
}
__device__ __forceinline__ void ldsm4t(uint32_t* r, uint32_t addr) {
    asm volatile("ldmatrix.sync.aligned.m8n8.x4.trans.shared.b16 {%0,%1,%2,%3}, [%4];"
        : "=r"(r[0]), "=r"(r[1]), "=r"(r[2]), "=r"(r[3]) : "r"(addr));
}
__device__ __forceinline__ void mma16816(float* c, const uint32_t* a,
                                         uint32_t b0, uint32_t b1) {
    asm volatile(
        "mma.sync.aligned.m16n8k16.row.col.f32.f16.f16.f32 "
        "{%0,%1,%2,%3}, {%4,%5,%6,%7}, {%8,%9}, {%0,%1,%2,%3};"
        : "+f"(c[0]), "+f"(c[1]), "+f"(c[2]), "+f"(c[3])
        : "r"(a[0]), "r"(a[1]), "r"(a[2]), "r"(a[3]), "r"(b0), "r"(b1));
}
__device__ __forceinline__ uint16_t to_fp16(float v) {
    __half hb = __float2half_rn(v);
    return *reinterpret_cast<uint16_t*>(&hb);
}

// -------- setup: weights -> fp16 word pairs -------------------------------
__global__ __launch_bounds__(256) void stageB_kernel(
    const float* __restrict__ w_off, const float* __restrict__ w_attn,
    const float* __restrict__ w_out)
{
    int idx = blockIdx.x * 256 + threadIdx.x;     // over 2*256*1152
    int gemm = idx / (256 * KW);
    int rem  = idx - gemm * (256 * KW);
    int row  = rem / KW;
    int wd   = rem - row * KW;
    int k    = wd * 2;
    float v0 = 0.f, v1 = 0.f;
    if (gemm == 0) {
        if (row < 144) {
            v0 = w_off[(size_t)row * KC + k];
            v1 = w_off[(size_t)row * KC + k + 1];
        } else if (row < CO1) {
            v0 = w_attn[(size_t)(row - 144) * KC + k];
            v1 = w_attn[(size_t)(row - 144) * KC + k + 1];
        }
    } else {
        v0 = w_out[(size_t)row * KC + k];
        v1 = w_out[(size_t)row * KC + k + 1];
    }
    g_Bw[gemm][row * KW + wd] =
        (uint32_t)to_fp16(v0) | ((uint32_t)to_fp16(v1) << 16);
}

// -------- main warp-MMA implicit GEMM (1-term fp16, K=64/iter) ------------
// CTA: 128 pixels x 256 channels, K = 2304. 512 threads / 16 warps (4m x 4n).
// EPI==0: A = im2col(x) computed in-kernel; B cp.async -> g_Y
// EPI==1: A & B pure cp.async copies -> NCHW out
template <int EPI>
__global__ __launch_bounds__(512, 1) void mma_kernel(
    const float* __restrict__ x,
    const float* __restrict__ ba,
    const float* __restrict__ bb,
    float* __restrict__ Cout)
{
    extern __shared__ __align__(16) char smem[];
    const uint32_t sb = smem_u32(smem);
    const int tid  = threadIdx.x;
    const int lane = tid & 31;
    const int wid  = tid >> 5;
    const int wm   = wid & 3;      // warp m-index (x32)
    const int wn   = wid >> 2;     // warp n-index (x64)
    const int m0   = blockIdx.x * 128;
    const int b    = m0 >> 12;

    // EPI0 producer mapping: (m, word w) for m and m+64
    const int pm = tid >> 3;       // 0..63
    const int pw = tid & 7;        // word 0..7 (k = c*16 + pw*2)

    // EPI1 A-copy mapping (threads 0..255): (k-row, 16B seg)
    const int cs  = tid & 15;            // seg
    const int ckl = (tid >> 4) & 15;     // k-row

    // ---- ldmatrix per-lane offsets (relative to stage bases) ----
    int offAh[2], offBh[4];
    if (EPI == 0) {
        const int rA   = lane & 15;
        const int segA = lane >> 4;
#pragma unroll
        for (int mt = 0; mt < 2; mt++) {
            int row = wm * 32 + mt * 16 + rA;
            offAh[mt] = row * 32 + (((segA * 4) ^ (rA & 4)) << 2);
        }
    } else {
        const int kr = (lane & 7) + ((lane & 16) ? 8 : 0);
        const int mo = (lane & 8) ? 1 : 0;
#pragma unroll
        for (int mt = 0; mt < 2; mt++) {
            int mseg = wm * 4 + mt * 2 + mo;
            offAh[mt] = kr * 256 + ((mseg ^ (kr & 7)) << 4);
        }
    }
    {
        const int rB   = (lane & 7) + ((lane & 16) ? 8 : 0);
        const int segB = (lane >> 3) & 1;
#pragma unroll
        for (int ntp = 0; ntp < 4; ntp++) {
            int row = wn * 64 + ntp * 16 + rB;
            offBh[ntp] = row * 32 + (((segB * 4) ^ (rB & 4)) << 2);
        }
    }

    // B-copy mapping: 512 threads x 16B = full 8KB plane
    const int bn = tid >> 1;
    const int bq = tid & 1;
    const int bdw = (bn * 8 + ((bq * 4) ^ (bn & 4))) * 4;  // byte offset in plane

    float cr[2][8][4];
#pragma unroll
    for (int mt = 0; mt < 2; mt++)
#pragma unroll
        for (int nt = 0; nt < 8; nt++)
#pragma unroll
            for (int j = 0; j < 4; j++) cr[mt][nt][j] = 0.f;

    const uint32_t* __restrict__ Bh = g_Bw[EPI];

    // ---- async producer: one chunk's copies (no commit) ----
    auto cpChunk = [&](int c) {
        if (c >= NCH) return;
        uint32_t dst = sb + (c & 15) * B_STG_B + bdw;
        cpasync16(dst, &Bh[bn * KW + c * 8 + bq * 4]);
        if (EPI == 1 && tid < 256) {
            uint32_t adst = sb + A_BASE + (c & 15) * A_STG_B
                          + ckl * 256 + ((cs ^ (ckl & 7)) << 4);
            const uint16_t* src = g_Ah
                + (size_t)(c * 16 + ckl) * NPIX + m0 + cs * 8;
            cpasync16(adst, src);
        }
    };
    auto cpB4 = [&](int c) {     // four chunks -> ONE commit group
        cpChunk(c);
        cpChunk(c + 1);
        cpChunk(c + 2);
        cpChunk(c + 3);
        CP_COMMIT();
    };

    // EPI0 split producer: LDG phase (issued before MMAs), STS phase (after)
    auto ldgA = [&](int c, float pv[2][2]) {
        if (EPI != 0 || c >= NCH) return;
#pragma unroll
        for (int half = 0; half < 2; half++) {
            const int mg = m0 + pm + half * 64;
            const int hh = (mg & 4095) >> 6;
            const int ww = mg & 63;
            const int k  = c * 16 + pw * 2;
#pragma unroll
            for (int u = 0; u < 2; u++) {
                int kk  = k + u;
                int ci  = kk / 9;
                int tap = kk - ci * 9;
                int dy = tap / 3 - 1, dx = tap - (tap / 3) * 3 - 1;
                int y = hh + dy, xx2 = ww + dx;
                pv[half][u] = ((unsigned)y < (unsigned)HH &&
                               (unsigned)xx2 < (unsigned)WW)
                    ? x[((size_t)(b * CC + ci) << 12) + (y << 6) + xx2] : 0.f;
            }
        }
    };
    auto stsA = [&](int c, float pv[2][2]) {
        if (EPI != 0 || c >= NCH) return;
        char* stp = smem + A_BASE + (c & 15) * A_STG_B;
#pragma unroll
        for (int half = 0; half < 2; half++) {
            const int m = pm + half * 64;
            int dw = m * 8 + (pw ^ (m & 4));
            *(uint32_t*)(stp + dw * 4) =
                (uint32_t)to_fp16(pv[half][0]) |
                ((uint32_t)to_fp16(pv[half][1]) << 16);
        }
    };

    // ---- consume one chunk ----
    auto consume = [&](int cc) {
        const uint32_t stbB = sb + (cc & 15) * B_STG_B;
        const uint32_t stbA = sb + A_BASE + (cc & 15) * A_STG_B;
        uint32_t ah[2][4];
#pragma unroll
        for (int mt = 0; mt < 2; mt++) {
            if (EPI == 0) ldsm4(ah[mt], stbA + offAh[mt]);
            else          ldsm4t(ah[mt], stbA + offAh[mt]);
        }
#pragma unroll
        for (int ntp = 0; ntp < 4; ntp++) {
            // GEMM0: channels >= 216 are zero padding -> skip (warp-uniform)
            if (EPI == 0 && wn * 64 + ntp * 16 >= CO1) continue;
            uint32_t bh[4];
            ldsm4(bh, stbB + offBh[ntp]);
#pragma unroll
            for (int j = 0; j < 2; j++) {
                const int nt = ntp * 2 + j;
                if (EPI == 0 && wn * 64 + ntp * 16 + j * 8 >= CO1) continue;
#pragma unroll
                for (int mt = 0; mt < 2; mt++)
                    mma16816(cr[mt][nt], ah[mt], bh[2 * j], bh[2 * j + 1]);
            }
        }
    };

    // ---- prologue: 3 groups (chunks 0-11) in flight; EPI0 stores A(0-3) ---
    cpB4(0); cpB4(4); cpB4(8);
    float pv[4][2][2];
    if (EPI == 0) {
#pragma unroll
        for (int q = 0; q < 4; q++) { ldgA(q, pv[q]); stsA(q, pv[q]); }
    }

    for (int c = 0; c < NCH; c += 4) {
        CP_WAIT2();               // chunks c..c+3 resident (<=2 groups pending)
        __syncthreads();          // + all warps done reading recycled stages

#pragma unroll
        for (int q = 0; q < 4; q++) ldgA(c + 4 + q, pv[q]);  // EPI0 gathers
        cpB4(c + 12);

        consume(c);
        consume(c + 1);
        consume(c + 2);
        consume(c + 3);

#pragma unroll
        for (int q = 0; q < 4; q++) stsA(c + 4 + q, pv[q]);  // EPI0 stores
    }
    CP_WAIT0();

    // ---- epilogue ----
    const int eg = lane >> 2;
    const int et = lane & 3;
#pragma unroll
    for (int mt = 0; mt < 2; mt++) {
#pragma unroll
        for (int nt = 0; nt < 8; nt++) {
            const float* cc = cr[mt][nt];
            int mloc = wm * 32 + mt * 16 + eg;
            int co   = wn * 64 + nt * 8 + et * 2;
#pragma unroll
            for (int rr = 0; rr < 2; rr++) {
                int m = m0 + mloc + rr * 8;
#pragma unroll
                for (int cw = 0; cw < 2; cw++) {
                    int c2 = co + cw;
                    float v = cc[rr * 2 + cw];
                    if (EPI == 0) {
                        if (c2 < CO1) {
                            float bias = (c2 < 144) ? ba[c2] : bb[c2 - 144];
                            g_Y[(size_t)c2 * NPIX + m] = v + bias;
                        }
                    } else {
                        Cout[((size_t)(b * OO + c2) << 12) + (m & 4095)] = v + ba[c2];
                    }
                }
            }
        }
    }
}

// -------- softmax + offsets -> packed bilinear weights/indices ------------
__global__ __launch_bounds__(256) void offmask_kernel() {
    int n = blockIdx.x * 256 + threadIdx.x;
    int g = blockIdx.y;
    int hw = n & 4095;
    int h = hw >> 6, w = hw & 63;

    float lg[KKT];
    float mx = -1e30f;
#pragma unroll
    for (int kk = 0; kk < KKT; kk++) {
        lg[kk] = g_Y[(size_t)(144 + g * KKT + kk) * NPIX + n];
        mx = fmaxf(mx, lg[kk]);
    }
    float s = 0.f;
#pragma unroll
    for (int kk = 0; kk < KKT; kk++) { lg[kk] = __expf(lg[kk] - mx); s += lg[kk]; }
    float inv = 1.f / s;

#pragma unroll
    for (int kk = 0; kk < KKT; kk++) {
        float a  = lg[kk] * inv;
        float dy = g_Y[(size_t)(g * 18 + 2 * kk    ) * NPIX + n];
        float dx = g_Y[(size_t)(g * 18 + 2 * kk + 1) * NPIX + n];
        float py = (float)(h - 1 + kk / 3) + dy;
        float px = (float)(w - 1 + kk % 3) + dx;

        float y0f = floorf(py), x0f = floorf(px);
        float fy = py - y0f, fx = px - x0f;
        y0f = fminf(fmaxf(y0f, -2.f), 65.f);
        x0f = fminf(fmaxf(x0f, -2.f), 65.f);
        int y0 = (int)y0f, x0 = (int)x0f;

        bool vy0 = (unsigned)y0       < (unsigned)HH;
        bool vy1 = (unsigned)(y0 + 1) < (unsigned)HH;
        bool vx0 = (unsigned)x0       < (unsigned)WW;
        bool vx1 = (unsigned)(x0 + 1) < (unsigned)WW;

        float w00 = (vy0 && vx0) ? (1.f - fy) * (1.f - fx) * a : 0.f;
        float w01 = (vy0 && vx1) ? (1.f - fy) * fx * a : 0.f;
        float w10 = (vy1 && vx0) ? fy * (1.f - fx) * a : 0.f;
        float w11 = (vy1 && vx1) ? fy * fx * a : 0.f;

        int r0  = min(max(y0,     0), HH - 1);
        int r1  = min(max(y0 + 1, 0), HH - 1);
        int cc0 = min(max(x0,     0), WW - 1);
        int cc1 = min(max(x0 + 1, 0), WW - 1);
        int pack = r0 | (r1 << 6) | (cc0 << 12) | (cc1 << 18);

        size_t o = (size_t)(g * KKT + kk) * NPIX + n;
        g_wq[o]  = make_float4(w00, w01, w10, w11);
        g_idx[o] = pack;
    }
}

// -------- sampler: wq/idx once per (pixel,g,tap), loop cg, write plane ----
__global__ __launch_bounds__(256) void sample_kernel(const float* __restrict__ x) {
    int n  = blockIdx.x * 256 + threadIdx.x;
    int gk = blockIdx.y;               // 0..71
    int g = gk / KKT, tap = gk - g * KKT;
    int b = n >> 12;

    size_t sidx = (size_t)gk * NPIX + n;
    float4 wq = g_wq[sidx];
    int pk = g_idx[sidx];
    int r0 = pk & 63, r1 = (pk >> 6) & 63;
    int c0 = (pk >> 12) & 63, c1 = (pk >> 18) & 63;
    int o00 = (r0 << 6) + c0, o01 = (r0 << 6) + c1;
    int o10 = (r1 << 6) + c0, o11 = (r1 << 6) + c1;

    const float* xb = x + ((size_t)(b * CC + g * CGR) << 12);
    const int kbase = g * 288 + tap;
#pragma unroll 4
    for (int cg = 0; cg < CGR; cg++) {
        const float* p = xb + ((size_t)cg << 12);
        float v = wq.x * p[o00] + wq.y * p[o01] + wq.z * p[o10] + wq.w * p[o11];
        g_Ah[(size_t)(kbase + cg * 9) * NPIX + n] = to_fp16(v);
    }
}

// --------------------------------------------------------------------------
extern "C" void kernel_launch(void* const* d_in, const int* in_sizes, int n_in,
                              void* d_out, int out_size) {
    const float* x      = nullptr;
    const float* w_off  = nullptr;
    const float* b_off  = nullptr;
    const float* w_attn = nullptr;
    const float* b_attn = nullptr;
    const float* w_out  = nullptr;
    const float* b_out  = nullptr;
    for (int i = 0; i < n_in; i++) {
        const float* p = (const float*)d_in[i];
        switch (in_sizes[i]) {
            case 8388608: x      = p; break;
            case 331776:  w_off  = p; break;
            case 144:     b_off  = p; break;
            case 165888:  w_attn = p; break;
            case 72:      b_attn = p; break;
            case 589824:  w_out  = p; break;
            case 256:     b_out  = p; break;
            default: break;
        }
    }
    if (!x || !w_off || !b_off || !w_attn || !b_attn || !w_out || !b_out)
        return;
    float* out = (float*)d_out;

    cudaFuncSetAttribute(mma_kernel<0>,
        cudaFuncAttributeMaxDynamicSharedMemorySize, SMEM_TOT);
    cudaFuncSetAttribute(mma_kernel<1>,
        cudaFuncAttributeMaxDynamicSharedMemorySize, SMEM_TOT);

    // 0) stage weights: fp32 -> fp16 word pairs
    stageB_kernel<<<(2 * 256 * KW) / 256, 256>>>(w_off, w_attn, w_out);

    // 1) offset/mask conv (HMMA 1-term, fused im2col, K=64/iter) -> g_Y
    mma_kernel<0><<<NPIX / 128, 512, SMEM_TOT>>>(x, b_off, b_attn, nullptr);

    // 2) softmax + packed bilinear weights/indices
    offmask_kernel<<<dim3(NPIX / 256, GG), 256>>>();

    // 3) sampling pass: modulated bilinear gather -> fp16 plane
    sample_kernel<<<dim3(NPIX / 256, GG * KKT), 256>>>(x);

    // 4) deformable conv (HMMA 1-term, A/B cp.async, K=64/iter) -> NCHW out
    mma_kernel<1><<<NPIX / 128, 512, SMEM_TOT>>>(x, b_out, nullptr, out);
}

// round 16
// speedup vs baseline: 2.6792x; 1.0255x over previous
#include <cuda_runtime.h>
#include <cuda_fp16.h>
#include <cstdint>
#include <cstddef>

#define BB 8
#define CC 256
#define HH 64
#define WW 64
#define GG 8
#define CGR 32
#define KKT 9
#define OO 256
#define NPIX (BB*HH*WW)        // 32768
#define KC (CC*KKT)            // 2304
#define KW (KC/2)              // 1152 b32 words per row
#define CO1 216
#define HWSZ (HH*WW)           // 4096
#define NCH (KC/16)            // 144 k16 steps

// ---- GEMM0 (unchanged shape): B 16 stages x 8KB; A 16 stages x 4KB ----
#define B_STG_B 8192
#define A_BASE  131072
#define A_STG_B 4096
#define SMEM_TOT (A_BASE + 16*A_STG_B)   // 196608

// ---- GEMM1 (n-split, 2 CTAs/SM): B 12 stages x 4KB; A 12 stages x 4KB ----
#define G1_BSTG  4096
#define G1_ABASE 49152
#define G1_ASTG  4096
#define G1_SMEM  (G1_ABASE + 12*G1_ASTG)  // 98304

// -------- scratch (static device globals) ---------------------------------
__device__ __align__(16) float    g_Y[(size_t)CO1 * NPIX];          // conv1 out
__device__ __align__(16) uint32_t g_Bw[2][256 * KW];                // weights fp16
__device__ __align__(16) uint16_t g_Ah[(size_t)KC * NPIX];          // sampled A fp16 plane

// -------- helpers ---------------------------------------------------------
__device__ __forceinline__ uint32_t smem_u32(const void* p) {
    uint32_t a;
    asm("{ .reg .u64 t; cvta.to.shared.u64 t, %1; cvt.u32.u64 %0, t; }"
        : "=r"(a) : "l"(p));
    return a;
}
__device__ __forceinline__ void cpasync16(uint32_t dst, const void* src) {
    asm volatile("cp.async.cg.shared.global [%0], [%1], 16;"
        :: "r"(dst), "l"(src) : "memory");
}
#define CP_COMMIT() asm volatile("cp.async.commit_group;" ::: "memory")
#define CP_WAIT1()  asm volatile("cp.async.wait_group 1;" ::: "memory")
#define CP_WAIT2()  asm volatile("cp.async.wait_group 2;" ::: "memory")
#define CP_WAIT0()  asm volatile("cp.async.wait_group 0;" ::: "memory")
__device__ __forceinline__ void ldsm4(uint32_t* r, uint32_t addr) {
    asm volatile("ldmatrix.sync.aligned.m8n8.x4.shared.b16 {%0,%1,%2,%3}, [%4];"
        : "=r"(r[0]), "=r"(r[1]), "=r"(r[2]), "=r"(r[3]) : "r"(addr));
}
__device__ __forceinline__ void ldsm4t(uint32_t* r, uint32_t addr) {
    asm volatile("ldmatrix.sync.aligned.m8n8.x4.trans.shared.b16 {%0,%1,%2,%3}, [%4];"
        : "=r"(r[0]), "=r"(r[1]), "=r"(r[2]), "=r"(r[3]) : "r"(addr));
}
__device__ __forceinline__ void mma16816(float* c, const uint32_t* a,
                                         uint32_t b0, uint32_t b1) {
    asm volatile(
        "mma.sync.aligned.m16n8k16.row.col.f32.f16.f16.f32 "
        "{%0,%1,%2,%3}, {%4,%5,%6,%7}, {%8,%9}, {%0,%1,%2,%3};"
        : "+f"(c[0]), "+f"(c[1]), "+f"(c[2]), "+f"(c[3])
        : "r"(a[0]), "r"(a[1]), "r"(a[2]), "r"(a[3]), "r"(b0), "r"(b1));
}
__device__ __forceinline__ uint16_t to_fp16(float v) {
    __half hb = __float2half_rn(v);
    return *reinterpret_cast<uint16_t*>(&hb);
}

// -------- setup: weights -> fp16 word pairs -------------------------------
__global__ __launch_bounds__(256) void stageB_kernel(
    const float* __restrict__ w_off, const float* __restrict__ w_attn,
    const float* __restrict__ w_out)
{
    int idx = blockIdx.x * 256 + threadIdx.x;     // over 2*256*1152
    int gemm = idx / (256 * KW);
    int rem  = idx - gemm * (256 * KW);
    int row  = rem / KW;
    int wd   = rem - row * KW;
    int k    = wd * 2;
    float v0 = 0.f, v1 = 0.f;
    if (gemm == 0) {
        if (row < 144) {
            v0 = w_off[(size_t)row * KC + k];
            v1 = w_off[(size_t)row * KC + k + 1];
        } else if (row < CO1) {
            v0 = w_attn[(size_t)(row - 144) * KC + k];
            v1 = w_attn[(size_t)(row - 144) * KC + k + 1];
        }
    } else {
        v0 = w_out[(size_t)row * KC + k];
        v1 = w_out[(size_t)row * KC + k + 1];
    }
    g_Bw[gemm][row * KW + wd] =
        (uint32_t)to_fp16(v0) | ((uint32_t)to_fp16(v1) << 16);
}

// -------- GEMM0: offset/mask conv (unchanged from R15 EPI0 path) ----------
// CTA: 128 pixels x 256 channels, 512 threads / 16 warps (4m x 4n), K=64/iter
__global__ __launch_bounds__(512, 1) void mma0_kernel(
    const float* __restrict__ x,
    const float* __restrict__ ba,
    const float* __restrict__ bb)
{
    extern __shared__ __align__(16) char smem[];
    const uint32_t sb = smem_u32(smem);
    const int tid  = threadIdx.x;
    const int lane = tid & 31;
    const int wid  = tid >> 5;
    const int wm   = wid & 3;
    const int wn   = wid >> 2;
    const int m0   = blockIdx.x * 128;
    const int b    = m0 >> 12;

    const int pm = tid >> 3;       // 0..63
    const int pw = tid & 7;        // word 0..7

    int offAh[2], offBh[4];
    {
        const int rA   = lane & 15;
        const int segA = lane >> 4;
#pragma unroll
        for (int mt = 0; mt < 2; mt++) {
            int row = wm * 32 + mt * 16 + rA;
            offAh[mt] = row * 32 + (((segA * 4) ^ (rA & 4)) << 2);
        }
        const int rB   = (lane & 7) + ((lane & 16) ? 8 : 0);
        const int segB = (lane >> 3) & 1;
#pragma unroll
        for (int ntp = 0; ntp < 4; ntp++) {
            int row = wn * 64 + ntp * 16 + rB;
            offBh[ntp] = row * 32 + (((segB * 4) ^ (rB & 4)) << 2);
        }
    }

    const int bn = tid >> 1;
    const int bq = tid & 1;
    const int bdw = (bn * 8 + ((bq * 4) ^ (bn & 4))) * 4;

    float cr[2][8][4];
#pragma unroll
    for (int mt = 0; mt < 2; mt++)
#pragma unroll
        for (int nt = 0; nt < 8; nt++)
#pragma unroll
            for (int j = 0; j < 4; j++) cr[mt][nt][j] = 0.f;

    const uint32_t* __restrict__ Bh = g_Bw[0];

    auto cpChunk = [&](int c) {
        if (c >= NCH) return;
        uint32_t dst = sb + (c & 15) * B_STG_B + bdw;
        cpasync16(dst, &Bh[bn * KW + c * 8 + bq * 4]);
    };
    auto cpB4 = [&](int c) {
        cpChunk(c); cpChunk(c + 1); cpChunk(c + 2); cpChunk(c + 3);
        CP_COMMIT();
    };

    auto ldgA = [&](int c, float pv[2][2]) {
        if (c >= NCH) return;
#pragma unroll
        for (int half = 0; half < 2; half++) {
            const int mg = m0 + pm + half * 64;
            const int hh = (mg & 4095) >> 6;
            const int ww = mg & 63;
            const int k  = c * 16 + pw * 2;
#pragma unroll
            for (int u = 0; u < 2; u++) {
                int kk  = k + u;
                int ci  = kk / 9;
                int tap = kk - ci * 9;
                int dy = tap / 3 - 1, dx = tap - (tap / 3) * 3 - 1;
                int y = hh + dy, xx2 = ww + dx;
                pv[half][u] = ((unsigned)y < (unsigned)HH &&
                               (unsigned)xx2 < (unsigned)WW)
                    ? x[((size_t)(b * CC + ci) << 12) + (y << 6) + xx2] : 0.f;
            }
        }
    };
    auto stsA = [&](int c, float pv[2][2]) {
        if (c >= NCH) return;
        char* stp = smem + A_BASE + (c & 15) * A_STG_B;
#pragma unroll
        for (int half = 0; half < 2; half++) {
            const int m = pm + half * 64;
            int dw = m * 8 + (pw ^ (m & 4));
            *(uint32_t*)(stp + dw * 4) =
                (uint32_t)to_fp16(pv[half][0]) |
                ((uint32_t)to_fp16(pv[half][1]) << 16);
        }
    };

    auto consume = [&](int cc) {
        const uint32_t stbB = sb + (cc & 15) * B_STG_B;
        const uint32_t stbA = sb + A_BASE + (cc & 15) * A_STG_B;
        uint32_t ah[2][4];
#pragma unroll
        for (int mt = 0; mt < 2; mt++) ldsm4(ah[mt], stbA + offAh[mt]);
#pragma unroll
        for (int ntp = 0; ntp < 4; ntp++) {
            if (wn * 64 + ntp * 16 >= CO1) continue;
            uint32_t bh[4];
            ldsm4(bh, stbB + offBh[ntp]);
#pragma unroll
            for (int j = 0; j < 2; j++) {
                const int nt = ntp * 2 + j;
                if (wn * 64 + ntp * 16 + j * 8 >= CO1) continue;
#pragma unroll
                for (int mt = 0; mt < 2; mt++)
                    mma16816(cr[mt][nt], ah[mt], bh[2 * j], bh[2 * j + 1]);
            }
        }
    };

    cpB4(0); cpB4(4); cpB4(8);
    float pv[4][2][2];
#pragma unroll
    for (int q = 0; q < 4; q++) { ldgA(q, pv[q]); stsA(q, pv[q]); }

    for (int c = 0; c < NCH; c += 4) {
        CP_WAIT2();
        __syncthreads();
#pragma unroll
        for (int q = 0; q < 4; q++) ldgA(c + 4 + q, pv[q]);
        cpB4(c + 12);
        consume(c); consume(c + 1); consume(c + 2); consume(c + 3);
#pragma unroll
        for (int q = 0; q < 4; q++) stsA(c + 4 + q, pv[q]);
    }
    CP_WAIT0();

    const int eg = lane >> 2;
    const int et = lane & 3;
#pragma unroll
    for (int mt = 0; mt < 2; mt++) {
#pragma unroll
        for (int nt = 0; nt < 8; nt++) {
            const float* cc = cr[mt][nt];
            int mloc = wm * 32 + mt * 16 + eg;
            int co   = wn * 64 + nt * 8 + et * 2;
#pragma unroll
            for (int rr = 0; rr < 2; rr++) {
                int m = m0 + mloc + rr * 8;
#pragma unroll
                for (int cw = 0; cw < 2; cw++) {
                    int c2 = co + cw;
                    if (c2 < CO1) {
                        float bias = (c2 < 144) ? ba[c2] : bb[c2 - 144];
                        g_Y[(size_t)c2 * NPIX + m] = cr[mt][nt][rr * 2 + cw] + bias;
                    }
                }
            }
        }
    }
}

// -------- merged softmax + offsets + bilinear sampler ---------------------
// One thread per (pixel, g): softmax over 9 taps, then tap x cg sampling.
__global__ __launch_bounds__(256) void offsamp_kernel(const float* __restrict__ x) {
    int n = blockIdx.x * 256 + threadIdx.x;
    int g = blockIdx.y;
    int hw = n & 4095;
    int h = hw >> 6, w = hw & 63;
    int b = n >> 12;

    float lg[KKT];
    float mx = -1e30f;
#pragma unroll
    for (int kk = 0; kk < KKT; kk++) {
        lg[kk] = g_Y[(size_t)(144 + g * KKT + kk) * NPIX + n];
        mx = fmaxf(mx, lg[kk]);
    }
    float s = 0.f;
#pragma unroll
    for (int kk = 0; kk < KKT; kk++) { lg[kk] = __expf(lg[kk] - mx); s += lg[kk]; }
    float inv = 1.f / s;

    const float* xb = x + ((size_t)(b * CC + g * CGR) << 12);

#pragma unroll 1
    for (int kk = 0; kk < KKT; kk++) {
        float a  = lg[kk] * inv;
        float dy = g_Y[(size_t)(g * 18 + 2 * kk    ) * NPIX + n];
        float dx = g_Y[(size_t)(g * 18 + 2 * kk + 1) * NPIX + n];
        float py = (float)(h - 1 + kk / 3) + dy;
        float px = (float)(w - 1 + kk % 3) + dx;

        float y0f = floorf(py), x0f = floorf(px);
        float fy = py - y0f, fx = px - x0f;
        y0f = fminf(fmaxf(y0f, -2.f), 65.f);
        x0f = fminf(fmaxf(x0f, -2.f), 65.f);
        int y0 = (int)y0f, x0 = (int)x0f;

        bool vy0 = (unsigned)y0       < (unsigned)HH;
        bool vy1 = (unsigned)(y0 + 1) < (unsigned)HH;
        bool vx0 = (unsigned)x0       < (unsigned)WW;
        bool vx1 = (unsigned)(x0 + 1) < (unsigned)WW;

        float w00 = (vy0 && vx0) ? (1.f - fy) * (1.f - fx) * a : 0.f;
        float w01 = (vy0 && vx1) ? (1.f - fy) * fx * a : 0.f;
        float w10 = (vy1 && vx0) ? fy * (1.f - fx) * a : 0.f;
        float w11 = (vy1 && vx1) ? fy * fx * a : 0.f;

        int r0  = min(max(y0,     0), HH - 1);
        int r1  = min(max(y0 + 1, 0), HH - 1);
        int cc0 = min(max(x0,     0), WW - 1);
        int cc1 = min(max(x0 + 1, 0), WW - 1);
        int o00 = (r0 << 6) + cc0, o01 = (r0 << 6) + cc1;
        int o10 = (r1 << 6) + cc0, o11 = (r1 << 6) + cc1;

        const int kbase = g * 288 + kk;
#pragma unroll 4
        for (int cg = 0; cg < CGR; cg++) {
            const float* p = xb + ((size_t)cg << 12);
            float v = w00 * p[o00] + w01 * p[o01] + w10 * p[o10] + w11 * p[o11];
            g_Ah[(size_t)(kbase + cg * 9) * NPIX + n] = to_fp16(v);
        }
    }
}

// -------- GEMM1: deformable conv, n-split, 2 CTAs/SM ----------------------
// CTA: 128 pixels x 128 channels, 256 threads / 8 warps (4m x 2n), K=64/iter
__global__ __launch_bounds__(256, 2) void gemm1_kernel(
    const float* __restrict__ ba,
    float* __restrict__ Cout)
{
    extern __shared__ __align__(16) char smem[];
    const uint32_t sb = smem_u32(smem);
    const int tid  = threadIdx.x;
    const int lane = tid & 31;
    const int wid  = tid >> 5;
    const int wm   = wid & 3;      // 4 m-warps (x32)
    const int wn   = wid >> 2;     // 2 n-warps (x64)
    const int m0   = blockIdx.x * 128;
    const int n0   = blockIdx.y * 128;
    const int b    = m0 >> 12;

    // A-copy mapping: 256 threads = 16 k-rows x 16 segs (16B each)
    const int cs  = tid & 15;
    const int ckl = tid >> 4;

    // ldmatrix offsets
    int offAh[2], offBh[4];
    {
        const int kr = (lane & 7) + ((lane & 16) ? 8 : 0);
        const int mo = (lane & 8) ? 1 : 0;
#pragma unroll
        for (int mt = 0; mt < 2; mt++) {
            int mseg = wm * 4 + mt * 2 + mo;
            offAh[mt] = kr * 256 + ((mseg ^ (kr & 7)) << 4);
        }
        const int rB   = (lane & 7) + ((lane & 16) ? 8 : 0);
        const int segB = (lane >> 3) & 1;
#pragma unroll
        for (int ntp = 0; ntp < 4; ntp++) {
            int row = wn * 64 + ntp * 16 + rB;
            offBh[ntp] = row * 32 + (((segB * 4) ^ (rB & 4)) << 2);
        }
    }

    // B-copy mapping: 256 threads = 128 rows x 2 segs (16B each) = 4KB/stage
    const int bn = tid >> 1;
    const int bq = tid & 1;
    const int bdw = (bn * 8 + ((bq * 4) ^ (bn & 4))) * 4;

    float cr[2][8][4];
#pragma unroll
    for (int mt = 0; mt < 2; mt++)
#pragma unroll
        for (int nt = 0; nt < 8; nt++)
#pragma unroll
            for (int j = 0; j < 4; j++) cr[mt][nt][j] = 0.f;

    const uint32_t* __restrict__ Bh = g_Bw[1];

    auto cpChunk = [&](int c) {
        if (c >= NCH) return;
        const int s = c % 12;
        cpasync16(sb + s * G1_BSTG + bdw,
                  &Bh[(size_t)(n0 + bn) * KW + c * 8 + bq * 4]);
        uint32_t adst = sb + G1_ABASE + s * G1_ASTG
                      + ckl * 256 + ((cs ^ (ckl & 7)) << 4);
        cpasync16(adst, g_Ah + (size_t)(c * 16 + ckl) * NPIX + m0 + cs * 8);
    };
    auto cpB4 = [&](int c) {
        cpChunk(c); cpChunk(c + 1); cpChunk(c + 2); cpChunk(c + 3);
        CP_COMMIT();
    };

    auto consume = [&](int cc) {
        const int s = cc % 12;
        const uint32_t stbB = sb + s * G1_BSTG;
        const uint32_t stbA = sb + G1_ABASE + s * G1_ASTG;
        uint32_t ah[2][4];
#pragma unroll
        for (int mt = 0; mt < 2; mt++) ldsm4t(ah[mt], stbA + offAh[mt]);
#pragma unroll
        for (int ntp = 0; ntp < 4; ntp++) {
            uint32_t bh[4];
            ldsm4(bh, stbB + offBh[ntp]);
#pragma unroll
            for (int j = 0; j < 2; j++) {
                const int nt = ntp * 2 + j;
#pragma unroll
                for (int mt = 0; mt < 2; mt++)
                    mma16816(cr[mt][nt], ah[mt], bh[2 * j], bh[2 * j + 1]);
            }
        }
    };

    // prologue: 2 groups (chunks 0-7) in flight
    cpB4(0); cpB4(4);

    for (int c = 0; c < NCH; c += 4) {
        CP_WAIT1();               // group covering chunks c..c+3 complete
        __syncthreads();          // all warps done with recycled stages
        cpB4(c + 8);              // stages (c+8..c+11)%12: disjoint from reads
        consume(c); consume(c + 1); consume(c + 2); consume(c + 3);
    }
    CP_WAIT0();

    // epilogue
    const int eg = lane >> 2;
    const int et = lane & 3;
#pragma unroll
    for (int mt = 0; mt < 2; mt++) {
#pragma unroll
        for (int nt = 0; nt < 8; nt++) {
            const float* cc = cr[mt][nt];
            int mloc = wm * 32 + mt * 16 + eg;
            int co   = n0 + wn * 64 + nt * 8 + et * 2;
#pragma unroll
            for (int rr = 0; rr < 2; rr++) {
                int m = m0 + mloc + rr * 8;
#pragma unroll
                for (int cw = 0; cw < 2; cw++) {
                    int c2 = co + cw;
                    Cout[((size_t)(b * OO + c2) << 12) + (m & 4095)]
                        = cc[rr * 2 + cw] + ba[c2];
                }
            }
        }
    }
}

// --------------------------------------------------------------------------
extern "C" void kernel_launch(void* const* d_in, const int* in_sizes, int n_in,
                              void* d_out, int out_size) {
    const float* x      = nullptr;
    const float* w_off  = nullptr;
    const float* b_off  = nullptr;
    const float* w_attn = nullptr;
    const float* b_attn = nullptr;
    const float* w_out  = nullptr;
    const float* b_out  = nullptr;
    for (int i = 0; i < n_in; i++) {
        const float* p = (const float*)d_in[i];
        switch (in_sizes[i]) {
            case 8388608: x      = p; break;
            case 331776:  w_off  = p; break;
            case 144:     b_off  = p; break;
            case 165888:  w_attn = p; break;
            case 72:      b_attn = p; break;
            case 589824:  w_out  = p; break;
            case 256:     b_out  = p; break;
            default: break;
        }
    }
    if (!x || !w_off || !b_off || !w_attn || !b_attn || !w_out || !b_out)
        return;
    float* out = (float*)d_out;

    cudaFuncSetAttribute(mma0_kernel,
        cudaFuncAttributeMaxDynamicSharedMemorySize, SMEM_TOT);
    cudaFuncSetAttribute(gemm1_kernel,
        cudaFuncAttributeMaxDynamicSharedMemorySize, G1_SMEM);

    // 0) stage weights: fp32 -> fp16 word pairs
    stageB_kernel<<<(2 * 256 * KW) / 256, 256>>>(w_off, w_attn, w_out);

    // 1) offset/mask conv (HMMA 1-term, fused im2col, K=64/iter) -> g_Y
    mma0_kernel<<<NPIX / 128, 512, SMEM_TOT>>>(x, b_off, b_attn);

    // 2) merged softmax + offsets + bilinear sampling -> fp16 A plane
    offsamp_kernel<<<dim3(NPIX / 256, GG), 256>>>(x);

    // 3) deformable conv (HMMA 1-term, n-split 2 CTAs/SM) -> NCHW out
    gemm1_kernel<<<dim3(NPIX / 128, 2), 256, G1_SMEM>>>(b_out, out);
}

// round 17
// speedup vs baseline: 2.7154x; 1.0135x over previous
#include <cuda_runtime.h>
#include <cuda_fp16.h>
#include <cstdint>
#include <cstddef>

#define BB 8
#define CC 256
#define HH 64
#define WW 64
#define GG 8
#define CGR 32
#define KKT 9
#define OO 256
#define NPIX (BB*HH*WW)        // 32768
#define KC (CC*KKT)            // 2304
#define KW (KC/2)              // 1152 b32 words per row
#define CO1 216
#define HWSZ (HH*WW)           // 4096
#define NCH (KC/16)            // 144 k16 steps

// ---- GEMM0: B 16 stages x 8KB; A 16 stages x 4KB ----
#define B_STG_B 8192
#define A_BASE  131072
#define A_STG_B 4096
#define SMEM_TOT (A_BASE + 16*A_STG_B)   // 196608

// ---- GEMM1 (n-split, 2 CTAs/SM): B 12 stages x 4KB; A 12 stages x 4KB ----
#define G1_BSTG  4096
#define G1_ABASE 49152
#define G1_ASTG  4096
#define G1_SMEM  (G1_ABASE + 12*G1_ASTG)  // 98304

// -------- scratch (static device globals) ---------------------------------
__device__ __align__(16) float    g_Y[(size_t)CO1 * NPIX];          // conv1 out
__device__ __align__(16) uint32_t g_Bw[2][256 * KW];                // weights fp16
__device__ __align__(16) uint16_t g_Ah[(size_t)KC * NPIX];          // sampled A fp16 plane

// -------- helpers ---------------------------------------------------------
__device__ __forceinline__ uint32_t smem_u32(const void* p) {
    uint32_t a;
    asm("{ .reg .u64 t; cvta.to.shared.u64 t, %1; cvt.u32.u64 %0, t; }"
        : "=r"(a) : "l"(p));
    return a;
}
__device__ __forceinline__ void cpasync16(uint32_t dst, const void* src) {
    asm volatile("cp.async.cg.shared.global [%0], [%1], 16;"
        :: "r"(dst), "l"(src) : "memory");
}
#define CP_COMMIT() asm volatile("cp.async.commit_group;" ::: "memory")
#define CP_WAIT1()  asm volatile("cp.async.wait_group 1;" ::: "memory")
#define CP_WAIT2()  asm volatile("cp.async.wait_group 2;" ::: "memory")
#define CP_WAIT0()  asm volatile("cp.async.wait_group 0;" ::: "memory")
__device__ __forceinline__ void ldsm4(uint32_t* r, uint32_t addr) {
    asm volatile("ldmatrix.sync.aligned.m8n8.x4.shared.b16 {%0,%1,%2,%3}, [%4];"
        : "=r"(r[0]), "=r"(r[1]), "=r"(r[2]), "=r"(r[3]) : "r"(addr));
}
__device__ __forceinline__ void ldsm4t(uint32_t* r, uint32_t addr) {
    asm volatile("ldmatrix.sync.aligned.m8n8.x4.trans.shared.b16 {%0,%1,%2,%3}, [%4];"
        : "=r"(r[0]), "=r"(r[1]), "=r"(r[2]), "=r"(r[3]) : "r"(addr));
}
__device__ __forceinline__ void mma16816(float* c, const uint32_t* a,
                                         uint32_t b0, uint32_t b1) {
    asm volatile(
        "mma.sync.aligned.m16n8k16.row.col.f32.f16.f16.f32 "
        "{%0,%1,%2,%3}, {%4,%5,%6,%7}, {%8,%9}, {%0,%1,%2,%3};"
        : "+f"(c[0]), "+f"(c[1]), "+f"(c[2]), "+f"(c[3])
        : "r"(a[0]), "r"(a[1]), "r"(a[2]), "r"(a[3]), "r"(b0), "r"(b1));
}
__device__ __forceinline__ uint16_t to_fp16(float v) {
    __half hb = __float2half_rn(v);
    return *reinterpret_cast<uint16_t*>(&hb);
}

// -------- setup: weights -> fp16 word pairs -------------------------------
__global__ __launch_bounds__(256) void stageB_kernel(
    const float* __restrict__ w_off, const float* __restrict__ w_attn,
    const float* __restrict__ w_out)
{
    int idx = blockIdx.x * 256 + threadIdx.x;     // over 2*256*1152
    int gemm = idx / (256 * KW);
    int rem  = idx - gemm * (256 * KW);
    int row  = rem / KW;
    int wd   = rem - row * KW;
    int k    = wd * 2;
    float v0 = 0.f, v1 = 0.f;
    if (gemm == 0) {
        if (row < 144) {
            v0 = w_off[(size_t)row * KC + k];
            v1 = w_off[(size_t)row * KC + k + 1];
        } else if (row < CO1) {
            v0 = w_attn[(size_t)(row - 144) * KC + k];
            v1 = w_attn[(size_t)(row - 144) * KC + k + 1];
        }
    } else {
        v0 = w_out[(size_t)row * KC + k];
        v1 = w_out[(size_t)row * KC + k + 1];
    }
    g_Bw[gemm][row * KW + wd] =
        (uint32_t)to_fp16(v0) | ((uint32_t)to_fp16(v1) << 16);
}

// -------- GEMM0: offset/mask conv (fused im2col, K=64/iter) ---------------
// CTA: 128 pixels x 256 channels, 512 threads / 16 warps (4m x 4n)
__global__ __launch_bounds__(512, 1) void mma0_kernel(
    const float* __restrict__ x,
    const float* __restrict__ ba,
    const float* __restrict__ bb)
{
    extern __shared__ __align__(16) char smem[];
    const uint32_t sb = smem_u32(smem);
    const int tid  = threadIdx.x;
    const int lane = tid & 31;
    const int wid  = tid >> 5;
    const int wm   = wid & 3;
    const int wn   = wid >> 2;
    const int m0   = blockIdx.x * 128;
    const int b    = m0 >> 12;

    const int pm = tid >> 3;       // 0..63
    const int pw = tid & 7;        // word 0..7

    int offAh[2], offBh[4];
    {
        const int rA   = lane & 15;
        const int segA = lane >> 4;
#pragma unroll
        for (int mt = 0; mt < 2; mt++) {
            int row = wm * 32 + mt * 16 + rA;
            offAh[mt] = row * 32 + (((segA * 4) ^ (rA & 4)) << 2);
        }
        const int rB   = (lane & 7) + ((lane & 16) ? 8 : 0);
        const int segB = (lane >> 3) & 1;
#pragma unroll
        for (int ntp = 0; ntp < 4; ntp++) {
            int row = wn * 64 + ntp * 16 + rB;
            offBh[ntp] = row * 32 + (((segB * 4) ^ (rB & 4)) << 2);
        }
    }

    const int bn = tid >> 1;
    const int bq = tid & 1;
    const int bdw = (bn * 8 + ((bq * 4) ^ (bn & 4))) * 4;

    float cr[2][8][4];
#pragma unroll
    for (int mt = 0; mt < 2; mt++)
#pragma unroll
        for (int nt = 0; nt < 8; nt++)
#pragma unroll
            for (int j = 0; j < 4; j++) cr[mt][nt][j] = 0.f;

    const uint32_t* __restrict__ Bh = g_Bw[0];

    auto cpChunk = [&](int c) {
        if (c >= NCH) return;
        uint32_t dst = sb + (c & 15) * B_STG_B + bdw;
        cpasync16(dst, &Bh[bn * KW + c * 8 + bq * 4]);
    };
    auto cpB4 = [&](int c) {
        cpChunk(c); cpChunk(c + 1); cpChunk(c + 2); cpChunk(c + 3);
        CP_COMMIT();
    };

    auto ldgA = [&](int c, float pv[2][2]) {
        if (c >= NCH) return;
#pragma unroll
        for (int half = 0; half < 2; half++) {
            const int mg = m0 + pm + half * 64;
            const int hh = (mg & 4095) >> 6;
            const int ww = mg & 63;
            const int k  = c * 16 + pw * 2;
#pragma unroll
            for (int u = 0; u < 2; u++) {
                int kk  = k + u;
                int ci  = kk / 9;
                int tap = kk - ci * 9;
                int dy = tap / 3 - 1, dx = tap - (tap / 3) * 3 - 1;
                int y = hh + dy, xx2 = ww + dx;
                pv[half][u] = ((unsigned)y < (unsigned)HH &&
                               (unsigned)xx2 < (unsigned)WW)
                    ? x[((size_t)(b * CC + ci) << 12) + (y << 6) + xx2] : 0.f;
            }
        }
    };
    auto stsA = [&](int c, float pv[2][2]) {
        if (c >= NCH) return;
        char* stp = smem + A_BASE + (c & 15) * A_STG_B;
#pragma unroll
        for (int half = 0; half < 2; half++) {
            const int m = pm + half * 64;
            int dw = m * 8 + (pw ^ (m & 4));
            *(uint32_t*)(stp + dw * 4) =
                (uint32_t)to_fp16(pv[half][0]) |
                ((uint32_t)to_fp16(pv[half][1]) << 16);
        }
    };

    auto consume = [&](int cc) {
        const uint32_t stbB = sb + (cc & 15) * B_STG_B;
        const uint32_t stbA = sb + A_BASE + (cc & 15) * A_STG_B;
        uint32_t ah[2][4];
#pragma unroll
        for (int mt = 0; mt < 2; mt++) ldsm4(ah[mt], stbA + offAh[mt]);
#pragma unroll
        for (int ntp = 0; ntp < 4; ntp++) {
            if (wn * 64 + ntp * 16 >= CO1) continue;
            uint32_t bh[4];
            ldsm4(bh, stbB + offBh[ntp]);
#pragma unroll
            for (int j = 0; j < 2; j++) {
                const int nt = ntp * 2 + j;
                if (wn * 64 + ntp * 16 + j * 8 >= CO1) continue;
#pragma unroll
                for (int mt = 0; mt < 2; mt++)
                    mma16816(cr[mt][nt], ah[mt], bh[2 * j], bh[2 * j + 1]);
            }
        }
    };

    cpB4(0); cpB4(4); cpB4(8);
    float pv[4][2][2];
#pragma unroll
    for (int q = 0; q < 4; q++) { ldgA(q, pv[q]); stsA(q, pv[q]); }

    for (int c = 0; c < NCH; c += 4) {
        CP_WAIT2();
        __syncthreads();
#pragma unroll
        for (int q = 0; q < 4; q++) ldgA(c + 4 + q, pv[q]);
        cpB4(c + 12);
        consume(c); consume(c + 1); consume(c + 2); consume(c + 3);
#pragma unroll
        for (int q = 0; q < 4; q++) stsA(c + 4 + q, pv[q]);
    }
    CP_WAIT0();

    const int eg = lane >> 2;
    const int et = lane & 3;
#pragma unroll
    for (int mt = 0; mt < 2; mt++) {
#pragma unroll
        for (int nt = 0; nt < 8; nt++) {
            int mloc = wm * 32 + mt * 16 + eg;
            int co   = wn * 64 + nt * 8 + et * 2;
#pragma unroll
            for (int rr = 0; rr < 2; rr++) {
                int m = m0 + mloc + rr * 8;
#pragma unroll
                for (int cw = 0; cw < 2; cw++) {
                    int c2 = co + cw;
                    if (c2 < CO1) {
                        float bias = (c2 < 144) ? ba[c2] : bb[c2 - 144];
                        g_Y[(size_t)c2 * NPIX + m] = cr[mt][nt][rr * 2 + cw] + bias;
                    }
                }
            }
        }
    }
}

// -------- fused softmax + offsets + sampler (2-phase, smem-staged) --------
// Block: 256 threads, 64 pixels x one g. Phase 1: 64 threads do softmax +
// bilinear weight/index computation -> smem. Phase 2: 256 threads =
// (4 cg-quads x 64 pixels) sample 9 taps x 8 cg each.
__global__ __launch_bounds__(256) void offsamp_kernel(const float* __restrict__ x) {
    __shared__ float4 s_wq[KKT][64];
    __shared__ int    s_idx[KKT][64];

    const int tid = threadIdx.x;
    const int g   = blockIdx.y;
    const int n0  = blockIdx.x * 64;
    const int b   = n0 >> 12;     // 64 pixels never cross an image boundary

    if (tid < 64) {
        const int n  = n0 + tid;
        const int hw = n & 4095;
        const int h = hw >> 6, w = hw & 63;

        float lg[KKT];
        float mx = -1e30f;
#pragma unroll
        for (int kk = 0; kk < KKT; kk++) {
            lg[kk] = g_Y[(size_t)(144 + g * KKT + kk) * NPIX + n];
            mx = fmaxf(mx, lg[kk]);
        }
        float s = 0.f;
#pragma unroll
        for (int kk = 0; kk < KKT; kk++) { lg[kk] = __expf(lg[kk] - mx); s += lg[kk]; }
        float inv = 1.f / s;

#pragma unroll
        for (int kk = 0; kk < KKT; kk++) {
            float a  = lg[kk] * inv;
            float dy = g_Y[(size_t)(g * 18 + 2 * kk    ) * NPIX + n];
            float dx = g_Y[(size_t)(g * 18 + 2 * kk + 1) * NPIX + n];
            float py = (float)(h - 1 + kk / 3) + dy;
            float px = (float)(w - 1 + kk % 3) + dx;

            float y0f = floorf(py), x0f = floorf(px);
            float fy = py - y0f, fx = px - x0f;
            y0f = fminf(fmaxf(y0f, -2.f), 65.f);
            x0f = fminf(fmaxf(x0f, -2.f), 65.f);
            int y0 = (int)y0f, x0 = (int)x0f;

            bool vy0 = (unsigned)y0       < (unsigned)HH;
            bool vy1 = (unsigned)(y0 + 1) < (unsigned)HH;
            bool vx0 = (unsigned)x0       < (unsigned)WW;
            bool vx1 = (unsigned)(x0 + 1) < (unsigned)WW;

            float w00 = (vy0 && vx0) ? (1.f - fy) * (1.f - fx) * a : 0.f;
            float w01 = (vy0 && vx1) ? (1.f - fy) * fx * a : 0.f;
            float w10 = (vy1 && vx0) ? fy * (1.f - fx) * a : 0.f;
            float w11 = (vy1 && vx1) ? fy * fx * a : 0.f;

            int r0  = min(max(y0,     0), HH - 1);
            int r1  = min(max(y0 + 1, 0), HH - 1);
            int cc0 = min(max(x0,     0), WW - 1);
            int cc1 = min(max(x0 + 1, 0), WW - 1);

            s_wq[kk][tid]  = make_float4(w00, w01, w10, w11);
            s_idx[kk][tid] = r0 | (r1 << 6) | (cc0 << 12) | (cc1 << 18);
        }
    }
    __syncthreads();

    const int cgq = tid >> 6;      // 0..3
    const int pix = tid & 63;
    const int n   = n0 + pix;
    const float* xb = x + ((size_t)(b * CC + g * CGR + cgq * 8) << 12);

#pragma unroll 1
    for (int kk = 0; kk < KKT; kk++) {
        float4 wq = s_wq[kk][pix];
        int pk = s_idx[kk][pix];
        int r0 = pk & 63, r1 = (pk >> 6) & 63;
        int c0 = (pk >> 12) & 63, c1 = (pk >> 18) & 63;
        int o00 = (r0 << 6) + c0, o01 = (r0 << 6) + c1;
        int o10 = (r1 << 6) + c0, o11 = (r1 << 6) + c1;

        const int kbase = g * 288 + cgq * 8 * 9 + kk;
#pragma unroll
        for (int cg8 = 0; cg8 < 8; cg8++) {
            const float* p = xb + ((size_t)cg8 << 12);
            float v = wq.x * p[o00] + wq.y * p[o01]
                    + wq.z * p[o10] + wq.w * p[o11];
            g_Ah[(size_t)(kbase + cg8 * 9) * NPIX + n] = to_fp16(v);
        }
    }
}

// -------- GEMM1: deformable conv, n-split, 2 CTAs/SM ----------------------
// CTA: 128 pixels x 128 channels, 256 threads / 8 warps (4m x 2n), K=64/iter
__global__ __launch_bounds__(256, 2) void gemm1_kernel(
    const float* __restrict__ ba,
    float* __restrict__ Cout)
{
    extern __shared__ __align__(16) char smem[];
    const uint32_t sb = smem_u32(smem);
    const int tid  = threadIdx.x;
    const int lane = tid & 31;
    const int wid  = tid >> 5;
    const int wm   = wid & 3;
    const int wn   = wid >> 2;
    const int m0   = blockIdx.x * 128;
    const int n0   = blockIdx.y * 128;
    const int b    = m0 >> 12;

    const int cs  = tid & 15;
    const int ckl = tid >> 4;

    int offAh[2], offBh[4];
    {
        const int kr = (lane & 7) + ((lane & 16) ? 8 : 0);
        const int mo = (lane & 8) ? 1 : 0;
#pragma unroll
        for (int mt = 0; mt < 2; mt++) {
            int mseg = wm * 4 + mt * 2 + mo;
            offAh[mt] = kr * 256 + ((mseg ^ (kr & 7)) << 4);
        }
        const int rB   = (lane & 7) + ((lane & 16) ? 8 : 0);
        const int segB = (lane >> 3) & 1;
#pragma unroll
        for (int ntp = 0; ntp < 4; ntp++) {
            int row = wn * 64 + ntp * 16 + rB;
            offBh[ntp] = row * 32 + (((segB * 4) ^ (rB & 4)) << 2);
        }
    }

    const int bn = tid >> 1;
    const int bq = tid & 1;
    const int bdw = (bn * 8 + ((bq * 4) ^ (bn & 4))) * 4;

    float cr[2][8][4];
#pragma unroll
    for (int mt = 0; mt < 2; mt++)
#pragma unroll
        for (int nt = 0; nt < 8; nt++)
#pragma unroll
            for (int j = 0; j < 4; j++) cr[mt][nt][j] = 0.f;

    const uint32_t* __restrict__ Bh = g_Bw[1];

    auto cpChunk = [&](int c) {
        if (c >= NCH) return;
        const int s = c % 12;
        cpasync16(sb + s * G1_BSTG + bdw,
                  &Bh[(size_t)(n0 + bn) * KW + c * 8 + bq * 4]);
        uint32_t adst = sb + G1_ABASE + s * G1_ASTG
                      + ckl * 256 + ((cs ^ (ckl & 7)) << 4);
        cpasync16(adst, g_Ah + (size_t)(c * 16 + ckl) * NPIX + m0 + cs * 8);
    };
    auto cpB4 = [&](int c) {
        cpChunk(c); cpChunk(c + 1); cpChunk(c + 2); cpChunk(c + 3);
        CP_COMMIT();
    };

    auto consume = [&](int cc) {
        const int s = cc % 12;
        const uint32_t stbB = sb + s * G1_BSTG;
        const uint32_t stbA = sb + G1_ABASE + s * G1_ASTG;
        uint32_t ah[2][4];
#pragma unroll
        for (int mt = 0; mt < 2; mt++) ldsm4t(ah[mt], stbA + offAh[mt]);
#pragma unroll
        for (int ntp = 0; ntp < 4; ntp++) {
            uint32_t bh[4];
            ldsm4(bh, stbB + offBh[ntp]);
#pragma unroll
            for (int j = 0; j < 2; j++) {
                const int nt = ntp * 2 + j;
#pragma unroll
                for (int mt = 0; mt < 2; mt++)
                    mma16816(cr[mt][nt], ah[mt], bh[2 * j], bh[2 * j + 1]);
            }
        }
    };

    cpB4(0); cpB4(4);

    for (int c = 0; c < NCH; c += 4) {
        CP_WAIT1();
        __syncthreads();
        cpB4(c + 8);
        consume(c); consume(c + 1); consume(c + 2); consume(c + 3);
    }
    CP_WAIT0();

    const int eg = lane >> 2;
    const int et = lane & 3;
#pragma unroll
    for (int mt = 0; mt < 2; mt++) {
#pragma unroll
        for (int nt = 0; nt < 8; nt++) {
            const float* cc = cr[mt][nt];
            int mloc = wm * 32 + mt * 16 + eg;
            int co   = n0 + wn * 64 + nt * 8 + et * 2;
#pragma unroll
            for (int rr = 0; rr < 2; rr++) {
                int m = m0 + mloc + rr * 8;
#pragma unroll
                for (int cw = 0; cw < 2; cw++) {
                    int c2 = co + cw;
                    Cout[((size_t)(b * OO + c2) << 12) + (m & 4095)]
                        = cc[rr * 2 + cw] + ba[c2];
                }
            }
        }
    }
}

// --------------------------------------------------------------------------
extern "C" void kernel_launch(void* const* d_in, const int* in_sizes, int n_in,
                              void* d_out, int out_size) {
    const float* x      = nullptr;
    const float* w_off  = nullptr;
    const float* b_off  = nullptr;
    const float* w_attn = nullptr;
    const float* b_attn = nullptr;
    const float* w_out  = nullptr;
    const float* b_out  = nullptr;
    for (int i = 0; i < n_in; i++) {
        const float* p = (const float*)d_in[i];
        switch (in_sizes[i]) {
            case 8388608: x      = p; break;
            case 331776:  w_off  = p; break;
            case 144:     b_off  = p; break;
            case 165888:  w_attn = p; break;
            case 72:      b_attn = p; break;
            case 589824:  w_out  = p; break;
            case 256:     b_out  = p; break;
            default: break;
        }
    }
    if (!x || !w_off || !b_off || !w_attn || !b_attn || !w_out || !b_out)
        return;
    float* out = (float*)d_out;

    cudaFuncSetAttribute(mma0_kernel,
        cudaFuncAttributeMaxDynamicSharedMemorySize, SMEM_TOT);
    cudaFuncSetAttribute(gemm1_kernel,
        cudaFuncAttributeMaxDynamicSharedMemorySize, G1_SMEM);

    // 0) stage weights: fp32 -> fp16 word pairs
    stageB_kernel<<<(2 * 256 * KW) / 256, 256>>>(w_off, w_attn, w_out);

    // 1) offset/mask conv (HMMA 1-term, fused im2col, K=64/iter) -> g_Y
    mma0_kernel<<<NPIX / 128, 512, SMEM_TOT>>>(x, b_off, b_attn);

    // 2) fused softmax + offsets + bilinear sampling (2-phase) -> fp16 plane
    offsamp_kernel<<<dim3(NPIX / 64, GG), 256>>>(x);

    // 3) deformable conv (HMMA 1-term, n-split 2 CTAs/SM) -> NCHW out
    gemm1_kernel<<<dim3(NPIX / 128, 2), 256, G1_SMEM>>>(b_out, out);
}